// round 7
// baseline (speedup 1.0000x reference)
#include <cuda_runtime.h>
#include <cuda_bf16.h>
#include <cstdint>

#define Bb    8
#define Nn    2048
#define Dd    512
#define HIDc  2048
#define DQK   128
#define GRP   256
#define Gg    8
#define NT    (Bb*Nn)
#define Ee    1024
#define KK    17

// ================= warp MMA / async helpers (sm_80+ portable) =================
__device__ __forceinline__ uint32_t smem_to_u32(const void* p) {
    uint32_t a;
    asm("{ .reg .u64 t; cvta.to.shared.u64 t, %1; cvt.u32.u64 %0, t; }" : "=r"(a) : "l"(p));
    return a;
}
__device__ __forceinline__ void ldsm4(uint32_t* r, uint32_t addr) {
    asm volatile("ldmatrix.sync.aligned.m8n8.x4.shared.b16 {%0,%1,%2,%3}, [%4];"
        : "=r"(r[0]), "=r"(r[1]), "=r"(r[2]), "=r"(r[3]) : "r"(addr));
}
__device__ __forceinline__ void mma16816(float* c, const uint32_t* a, uint32_t b0, uint32_t b1) {
    asm volatile(
        "mma.sync.aligned.m16n8k16.row.col.f32.bf16.bf16.f32 "
        "{%0,%1,%2,%3}, {%4,%5,%6,%7}, {%8,%9}, {%0,%1,%2,%3};"
        : "+f"(c[0]), "+f"(c[1]), "+f"(c[2]), "+f"(c[3])
        : "r"(a[0]), "r"(a[1]), "r"(a[2]), "r"(a[3]), "r"(b0), "r"(b1));
}
__device__ __forceinline__ void cp16(uint32_t dst, const void* src) {
    asm volatile("cp.async.cg.shared.global [%0], [%1], 16;" :: "r"(dst), "l"(src));
}
#define CP_COMMIT() asm volatile("cp.async.commit_group;" ::: "memory")
#define CP_WAIT(N)  asm volatile("cp.async.wait_group %0;" :: "n"(N) : "memory")

#define F_SILU  1
#define F_ACC   2
#define F_SCORE 4
#define F_TRC   8

// ================= scratch pool =================
#define SZF(n) ((size_t)(n)*4)
#define SZB(n) ((size_t)(n)*2)
static constexpr size_t O_NX   = 0;
static constexpr size_t O_LNH  = O_NX   + SZF((size_t)NT*512);
static constexpr size_t O_LNL  = O_LNH  + SZB((size_t)NT*1024);
static constexpr size_t O_WHTH = O_LNL  + SZB((size_t)NT*1024);
static constexpr size_t O_WHTL = O_WHTH + SZB(2048*512);
static constexpr size_t O_WQTH = O_WHTL + SZB(2048*512);
static constexpr size_t O_WQTL = O_WQTH + SZB(128*512);
static constexpr size_t O_WOTH = O_WQTL + SZB(128*512);
static constexpr size_t O_WOTL = O_WOTH + SZB(512*1024);
static constexpr size_t O_BUFA = O_WOTL + SZB(512*1024);
static constexpr size_t O_HID  = O_BUFA + SZF((size_t)NT*2048);
static constexpr size_t O_HTH  = O_HID  + SZF((size_t)NT*2048);
static constexpr size_t O_HTL  = O_HTH  + SZB((size_t)NT*2048);
static constexpr size_t O_QK   = O_HTL  + SZB((size_t)NT*2048);
static constexpr size_t O_QK2  = O_QK   + SZF((size_t)NT*128);
static constexpr size_t O_QQH  = O_QK2  + SZF((size_t)NT*128);
static constexpr size_t O_QQL  = O_QQH  + SZB((size_t)NT*128);
static constexpr size_t O_LQH  = O_QQL  + SZB((size_t)NT*128);
static constexpr size_t O_LQL  = O_LQH  + SZB((size_t)NT*128);
static constexpr size_t O_QKH  = O_LQL  + SZB((size_t)NT*128);
static constexpr size_t O_QKL  = O_QKH  + SZB((size_t)NT*128);
static constexpr size_t O_LKF  = O_QKL  + SZB((size_t)NT*128);
static constexpr size_t O_LKTH = O_LKF  + SZF((size_t)NT*128);
static constexpr size_t O_LKTL = O_LKTH + SZB((size_t)NT*128);
static constexpr size_t O_ATTH = O_LKTL + SZB((size_t)NT*128);
static constexpr size_t O_ATTL = O_ATTH + SZB((size_t)64*256*256);
static constexpr size_t O_KVF  = O_ATTL + SZB((size_t)64*256*256);
static constexpr size_t O_KVH  = O_KVF  + SZF((size_t)64*2048*128);
static constexpr size_t O_KVL  = O_KVH  + SZB((size_t)64*2048*128);
static constexpr size_t O_END  = O_KVL  + SZB((size_t)64*2048*128);
__device__ __align__(1024) unsigned char g_pool[O_END];

__device__ __forceinline__ void bsplit(float v, __nv_bfloat16* h, __nv_bfloat16* l) {
    __nv_bfloat16 hv = __float2bfloat16(v);
    *h = hv;
    *l = __float2bfloat16(v - __bfloat162float(hv));
}
__device__ __forceinline__ void bsplit2(float v0, float v1, uint32_t& hu, uint32_t& lu) {
    __nv_bfloat16 h0 = __float2bfloat16(v0), h1 = __float2bfloat16(v1);
    __nv_bfloat16 l0 = __float2bfloat16(v0 - __bfloat162float(h0));
    __nv_bfloat16 l1 = __float2bfloat16(v1 - __bfloat162float(h1));
    hu = ((uint32_t)__bfloat16_as_ushort(h1) << 16) | __bfloat16_as_ushort(h0);
    lu = ((uint32_t)__bfloat16_as_ushort(l1) << 16) | __bfloat16_as_ushort(l0);
}

// ================= elementwise / prep kernels =================
__global__ void shift_k(const float4* __restrict__ x, float4* __restrict__ nx) {
    long i = (long)blockIdx.x * blockDim.x + threadIdx.x;
    if (i >= (long)NT*(Dd/4)) return;
    int c4 = (int)(i % (Dd/4));
    int n  = (int)((i / (Dd/4)) % Nn);
    if (c4 < Dd/8) nx[i] = (n == 0) ? make_float4(0,0,0,0) : x[i - Dd/4];
    else           nx[i] = x[i];
}

__global__ void ln_split_k(const float* __restrict__ in, const float* __restrict__ g,
                           const float* __restrict__ b,
                           __nv_bfloat16* __restrict__ oh, __nv_bfloat16* __restrict__ ol,
                           int C) {
    long row = blockIdx.x;
    const float2* xr2 = (const float2*)(in + row * C);
    int C2 = C >> 1;
    float s = 0.f, s2 = 0.f;
    for (int i = threadIdx.x; i < C2; i += blockDim.x) {
        float2 v = xr2[i]; s += v.x + v.y; s2 += v.x*v.x + v.y*v.y;
    }
    #pragma unroll
    for (int o = 16; o; o >>= 1) {
        s  += __shfl_xor_sync(~0u, s,  o);
        s2 += __shfl_xor_sync(~0u, s2, o);
    }
    __shared__ float shs[8], shs2[8], smu, sinv;
    int w = threadIdx.x >> 5, l = threadIdx.x & 31;
    if (l == 0) { shs[w] = s; shs2[w] = s2; }
    __syncthreads();
    if (threadIdx.x == 0) {
        float ts = 0.f, ts2 = 0.f;
        for (int i = 0; i < (int)(blockDim.x >> 5); i++) { ts += shs[i]; ts2 += shs2[i]; }
        float mu = ts / C;
        smu = mu; sinv = rsqrtf(ts2 / C - mu*mu + 1e-5f);
    }
    __syncthreads();
    float mu = smu, inv = sinv;
    uint32_t* oh2 = (uint32_t*)(oh + row*C);
    uint32_t* ol2 = (uint32_t*)(ol + row*C);
    const float2* g2 = (const float2*)g;
    const float2* b2 = (const float2*)b;
    for (int i = threadIdx.x; i < C2; i += blockDim.x) {
        float2 xv = xr2[i], gv = g2[i], bv = b2[i];
        float v0 = (xv.x - mu) * inv * gv.x + bv.x;
        float v1 = (xv.y - mu) * inv * gv.y + bv.y;
        uint32_t hu, lu;
        bsplit2(v0, v1, hu, lu);
        oh2[i] = hu; ol2[i] = lu;
    }
}

// fused gating + LN(1024) -> bf16 hi/lo
__global__ void gate_ln_k(const float* __restrict__ att, const float* __restrict__ hid,
                          const float* __restrict__ g, const float* __restrict__ b,
                          __nv_bfloat16* __restrict__ oh, __nv_bfloat16* __restrict__ ol) {
    long row = blockIdx.x;
    __shared__ float buf[1024];
    const float2* ar  = (const float2*)(att + row*HIDc);
    const float2* ar2 = (const float2*)(att + row*HIDc + Ee);
    const float2* hr  = (const float2*)(hid + row*HIDc);
    const float2* hr2 = (const float2*)(hid + row*HIDc + Ee);
    float s = 0.f, s2 = 0.f;
    for (int i = threadIdx.x; i < 512; i += blockDim.x) {
        float2 av = ar[i], au = ar2[i], v = hr[i], u = hr2[i];
        float t0 = au.x * v.x * (1.f / (1.f + expf(-(av.x * u.x))));
        float t1 = au.y * v.y * (1.f / (1.f + expf(-(av.y * u.y))));
        buf[2*i] = t0; buf[2*i+1] = t1;
        s += t0 + t1; s2 += t0*t0 + t1*t1;
    }
    #pragma unroll
    for (int o = 16; o; o >>= 1) {
        s  += __shfl_xor_sync(~0u, s,  o);
        s2 += __shfl_xor_sync(~0u, s2, o);
    }
    __shared__ float shs[8], shs2[8], smu, sinv;
    int w = threadIdx.x >> 5, l = threadIdx.x & 31;
    if (l == 0) { shs[w] = s; shs2[w] = s2; }
    __syncthreads();
    if (threadIdx.x == 0) {
        float ts = 0.f, ts2 = 0.f;
        for (int i = 0; i < (int)(blockDim.x >> 5); i++) { ts += shs[i]; ts2 += shs2[i]; }
        float mu = ts / 1024.f;
        smu = mu; sinv = rsqrtf(ts2 / 1024.f - mu*mu + 1e-5f);
    }
    __syncthreads();
    float mu = smu, inv = sinv;
    uint32_t* oh2 = (uint32_t*)(oh + row*1024);
    uint32_t* ol2 = (uint32_t*)(ol + row*1024);
    for (int i = threadIdx.x; i < 512; i += blockDim.x) {
        float v0 = (buf[2*i]   - mu) * inv * g[2*i]   + b[2*i];
        float v1 = (buf[2*i+1] - mu) * inv * g[2*i+1] + b[2*i+1];
        uint32_t hu, lu;
        bsplit2(v0, v1, hu, lu);
        oh2[i] = hu; ol2[i] = lu;
    }
}

// vectorized transpose fp32 [R,C] -> bf16 hi/lo [C,R], batched via blockIdx.z
__global__ void trans_split_k(const float* __restrict__ in,
                              __nv_bfloat16* __restrict__ oh, __nv_bfloat16* __restrict__ ol,
                              int R, int C) {
    __shared__ float s[32][36];
    size_t bz = (size_t)blockIdx.z * R * C;
    int c0 = blockIdx.x * 32, r0 = blockIdx.y * 32;
    int t = threadIdx.x;
    {
        int r = t >> 3, c4 = (t & 7) * 4;
        *(float4*)&s[r][c4] = *(const float4*)(in + bz + (size_t)(r0 + r)*C + c0 + c4);
    }
    __syncthreads();
    {
        int c = t & 31, rg = (t >> 5) * 4;
        float v0 = s[rg][c], v1 = s[rg+1][c], v2 = s[rg+2][c], v3 = s[rg+3][c];
        uint32_t h01, l01, h23, l23;
        bsplit2(v0, v1, h01, l01);
        bsplit2(v2, v3, h23, l23);
        size_t o = bz + (size_t)(c0 + c)*R + r0 + rg;
        *(uint2*)(oh + o) = make_uint2(h01, h23);
        *(uint2*)(ol + o) = make_uint2(l01, l23);
    }
}

// float4-vectorized depthwise conv K=17 + residual (+ optional extra residual)
__global__ void dwconv4_k(const float4* __restrict__ h4, const float* __restrict__ dw,
                          const float4* __restrict__ extra4, float4* __restrict__ out4, int C) {
    const int CT4 = 16, NTile = 128, HALO = 8;
    __shared__ float4 sh[NTile + 2*HALO][CT4];
    __shared__ float4 sdw[KK][CT4];
    int b = blockIdx.z, n0 = blockIdx.y * NTile, c0 = blockIdx.x * CT4;
    int C4 = C >> 2;
    const float4* base = h4 + (size_t)b*Nn*C4 + c0;
    for (int idx = threadIdx.x; idx < (NTile + 2*HALO)*CT4; idx += blockDim.x) {
        int r = idx >> 4, c = idx & 15;
        int n = n0 - HALO + r;
        sh[r][c] = (n >= 0 && n < Nn) ? base[(size_t)n*C4 + c] : make_float4(0,0,0,0);
    }
    for (int idx = threadIdx.x; idx < KK*CT4; idx += blockDim.x) {
        int k = idx >> 4, c = idx & 15;
        const float* w = dw + k*C + (c0 + c)*4;
        sdw[k][c] = make_float4(w[0], w[1], w[2], w[3]);
    }
    __syncthreads();
    for (int idx = threadIdx.x; idx < NTile*CT4; idx += blockDim.x) {
        int r = idx >> 4, c = idx & 15;
        float4 acc = sh[r + HALO][c];
        #pragma unroll
        for (int k = 0; k < KK; k++) {
            float4 a = sh[r + k][c], w = sdw[k][c];
            acc.x += a.x*w.x; acc.y += a.y*w.y; acc.z += a.z*w.z; acc.w += a.w*w.w;
        }
        size_t o = (size_t)b*Nn*C4 + (size_t)(n0 + r)*C4 + c0 + c;
        if (extra4) {
            float4 e = extra4[o];
            acc.x += e.x; acc.y += e.y; acc.z += e.z; acc.w += e.w;
        }
        out4[o] = acc;
    }
}

__global__ void qsplit_k(const float* __restrict__ qk, const float* __restrict__ gamma,
                         const float* __restrict__ beta,
                         __nv_bfloat16* qqh, __nv_bfloat16* qql,
                         __nv_bfloat16* lqh, __nv_bfloat16* lql,
                         __nv_bfloat16* qkh, __nv_bfloat16* qkl,
                         float* lkf) {
    long i2 = (long)blockIdx.x * blockDim.x + threadIdx.x;      // over NT*DQK/2
    if (i2 >= (long)NT*DQK/2) return;
    int d = (int)((i2 & 63) * 2);
    float2 v = ((const float2*)qk)[i2];
    uint32_t hu, lu;
    float a0, a1;
    a0 = v.x * gamma[0*DQK + d] + beta[0*DQK + d];
    a1 = v.y * gamma[0*DQK + d+1] + beta[0*DQK + d+1];
    bsplit2(a0, a1, hu, lu);
    ((uint32_t*)qqh)[i2] = hu; ((uint32_t*)qql)[i2] = lu;
    a0 = v.x * gamma[1*DQK + d] + beta[1*DQK + d];
    a1 = v.y * gamma[1*DQK + d+1] + beta[1*DQK + d+1];
    bsplit2(a0, a1, hu, lu);
    ((uint32_t*)lqh)[i2] = hu; ((uint32_t*)lql)[i2] = lu;
    a0 = v.x * gamma[2*DQK + d] + beta[2*DQK + d];
    a1 = v.y * gamma[2*DQK + d+1] + beta[2*DQK + d+1];
    bsplit2(a0, a1, hu, lu);
    ((uint32_t*)qkh)[i2] = hu; ((uint32_t*)qkl)[i2] = lu;
    float2 lk;
    lk.x = v.x * gamma[3*DQK + d] + beta[3*DQK + d];
    lk.y = v.y * gamma[3*DQK + d+1] + beta[3*DQK + d+1];
    ((float2*)lkf)[i2] = lk;
}

__global__ void cumsum_split_k(const float* __restrict__ kvf,
                               __nv_bfloat16* __restrict__ oh,
                               __nv_bfloat16* __restrict__ ol) {
    const size_t S = (size_t)2048*128;
    long i2 = (long)blockIdx.x * blockDim.x + threadIdx.x;      // over Bb*S/2
    if (i2 >= (long)Bb*(S/2)) return;
    size_t b = (size_t)i2 / (S/2), r2 = (size_t)i2 % (S/2);
    size_t base2 = b*Gg*(S/2) + r2;
    float s0 = 0.f, s1 = 0.f;
    #pragma unroll
    for (int g = 0; g < Gg; g++) {
        size_t o2 = base2 + (size_t)g*(S/2);
        float2 v = ((const float2*)kvf)[o2];
        uint32_t hu, lu;
        bsplit2(s0, s1, hu, lu);
        ((uint32_t*)oh)[o2] = hu; ((uint32_t*)ol)[o2] = lu;
        s0 += v.x; s1 += v.y;
    }
}

// ================= HMMA bf16x3 GEMM — fused hi/lo staging, 3-stage pipeline ======
// Stage row layout (144 B): cols 0-31 = hi chunk, cols 32-63 = lo chunk (K-chunk = 32).
#define LDA 72            // bf16 elems per smem row (64 data + 8 pad) = 144 B
#define STG_BYTES 36864   // one stage: A (18432) + B (18432)
#define NSTG 3
#define GSMEM (NSTG*STG_BYTES)

__global__ void __launch_bounds__(256, 2) gemm_k(
    const __nv_bfloat16* __restrict__ Ah, const __nv_bfloat16* __restrict__ Al,
    const __nv_bfloat16* __restrict__ Bh, const __nv_bfloat16* __restrict__ Bl,
    float* C, __nv_bfloat16* Ch, __nv_bfloat16* Cl,
    int M, int N, int Ktot, const float* __restrict__ bias, float alpha, int flags,
    long long sA, long long sB, long long sC)
{
    extern __shared__ __align__(16) unsigned char smem[];
    uint32_t sbase = smem_to_u32(smem);
    int tid = threadIdx.x, lane = tid & 31, wid = tid >> 5;
    int wm = wid & 3, wn = wid >> 2;            // 4 (M) x 2 (N) warps
    int brow = blockIdx.y * 128, bcol = blockIdx.x * 128;
    long long bz = blockIdx.z;
    Ah += bz*sA; Al += bz*sA; Bh += bz*sB; Bl += bz*sB;
    if (C)  C  += bz*sC;
    if (Ch) { Ch += bz*sC; Cl += bz*sC; }

    // fully-masked score tile: zero-fill and exit
    if ((flags & F_SCORE) && bcol > brow) {
        uint4 z = make_uint4(0,0,0,0);
        for (int e = tid; e < 2048; e += 256) {
            int row = e >> 4, seg = e & 15;
            *(uint4*)(Ch + (size_t)(brow + row)*N + bcol + seg*8) = z;
            *(uint4*)(Cl + (size_t)(brow + row)*N + bcol + seg*8) = z;
        }
        return;
    }

    float acc[2][8][4];
    #pragma unroll
    for (int i = 0; i < 2; i++)
        #pragma unroll
        for (int j = 0; j < 8; j++)
            #pragma unroll
            for (int q = 0; q < 4; q++) acc[i][j][q] = 0.f;

    uint32_t aOff = (uint32_t)(((wm*32 + (lane & 15)) * LDA + (lane >> 4)*8) * 2);
    uint32_t bOff = (uint32_t)(((wn*64 + ((lane >> 4) & 1)*8 + (lane & 7)) * LDA
                                + ((lane >> 3) & 1)*8) * 2) + 18432;
    const int ldr = tid >> 3, lds2 = tid & 7;
    const int seg = lds2 & 3;

    const int KC = Ktot >> 5;                   // 32-K chunks (hi+lo staged together)

    auto issue = [&](int it) {
        if (it < KC) {
            int k0 = it << 5;
            const __nv_bfloat16* As = (lds2 < 4) ? Ah : Al;
            const __nv_bfloat16* Bs = (lds2 < 4) ? Bh : Bl;
            uint32_t sa = sbase + (uint32_t)(it % NSTG)*STG_BYTES;
            #pragma unroll
            for (int e = 0; e < 4; e++) {
                int r = ldr + e*32;
                cp16(sa + (uint32_t)(r*144 + lds2*16),
                     As + (size_t)(brow + r)*Ktot + k0 + seg*8);
                cp16(sa + 18432u + (uint32_t)(r*144 + lds2*16),
                     Bs + (size_t)(bcol + r)*Ktot + k0 + seg*8);
            }
        }
        CP_COMMIT();
    };

    issue(0); issue(1);
    for (int it = 0; it < KC; ++it) {
        CP_WAIT(1);
        __syncthreads();
        issue(it + 2);
        uint32_t stg = sbase + (uint32_t)(it % NSTG)*STG_BYTES;
        uint32_t aB = stg + aOff, bB = stg + bOff;
        #pragma unroll
        for (int kk = 0; kk < 2; kk++) {
            uint32_t afh[2][4], afl[2][4];
            #pragma unroll
            for (int i = 0; i < 2; i++) {
                ldsm4(afh[i], aB + (uint32_t)((i*16*LDA + kk*16) * 2));
                ldsm4(afl[i], aB + (uint32_t)((i*16*LDA + 32 + kk*16) * 2));
            }
            #pragma unroll
            for (int p = 0; p < 4; p++) {
                uint32_t bh[4], bl[4];
                ldsm4(bh, bB + (uint32_t)((p*16*LDA + kk*16) * 2));
                ldsm4(bl, bB + (uint32_t)((p*16*LDA + 32 + kk*16) * 2));
                #pragma unroll
                for (int i = 0; i < 2; i++) {
                    mma16816(acc[i][2*p],   afh[i], bh[0], bh[1]);
                    mma16816(acc[i][2*p+1], afh[i], bh[2], bh[3]);
                    mma16816(acc[i][2*p],   afl[i], bh[0], bh[1]);
                    mma16816(acc[i][2*p+1], afl[i], bh[2], bh[3]);
                    mma16816(acc[i][2*p],   afh[i], bl[0], bl[1]);
                    mma16816(acc[i][2*p+1], afh[i], bl[2], bl[3]);
                }
            }
        }
    }

    // ---- epilogue ----
    int g = lane >> 2, c2 = (lane & 3)*2;
    #pragma unroll
    for (int i = 0; i < 2; i++) {
        #pragma unroll
        for (int j = 0; j < 8; j++) {
            #pragma unroll
            for (int rr = 0; rr < 2; rr++) {
                int row = brow + wm*32 + i*16 + g + rr*8;
                int col = bcol + wn*64 + j*8 + c2;
                float v0 = acc[i][j][rr*2+0] * alpha;
                float v1 = acc[i][j][rr*2+1] * alpha;
                if (flags & F_SCORE) {
                    v0 = fmaxf(v0, 0.f); v0 *= v0;
                    v1 = fmaxf(v1, 0.f); v1 *= v1;
                    if (col     > row) v0 = 0.f;
                    if (col + 1 > row) v1 = 0.f;
                    size_t o = (size_t)row*N + col;
                    uint32_t hu, lu;
                    bsplit2(v0, v1, hu, lu);
                    *(uint32_t*)(Ch + o) = hu;
                    *(uint32_t*)(Cl + o) = lu;
                } else if (flags & F_TRC) {
                    C[(size_t)col*M + row]     = v0;
                    C[(size_t)(col+1)*M + row] = v1;
                } else {
                    if (bias) { v0 += bias[col]; v1 += bias[col+1]; }
                    if (flags & F_SILU) {
                        v0 = v0 / (1.f + expf(-v0));
                        v1 = v1 / (1.f + expf(-v1));
                    }
                    size_t o = (size_t)row*N + col;
                    if (flags & F_ACC) { v0 += C[o]; v1 += C[o+1]; }
                    *(float2*)(C + o) = make_float2(v0, v1);
                }
            }
        }
    }
}

// ================= launcher =================
extern "C" void kernel_launch(void* const* d_in, const int* in_sizes, int n_in,
                              void* d_out, int out_size) {
    const float* x      = (const float*)d_in[0];
    const float* ln_h_g = (const float*)d_in[1];
    const float* ln_h_b = (const float*)d_in[2];
    const float* W_h    = (const float*)d_in[3];
    const float* b_h    = (const float*)d_in[4];
    const float* dw_h   = (const float*)d_in[5];
    const float* ln_qk_g= (const float*)d_in[6];
    const float* ln_qk_b= (const float*)d_in[7];
    const float* W_qk   = (const float*)d_in[8];
    const float* b_qk   = (const float*)d_in[9];
    const float* dw_qk  = (const float*)d_in[10];
    const float* gamma  = (const float*)d_in[11];
    const float* beta   = (const float*)d_in[12];
    const float* ln_o_g = (const float*)d_in[13];
    const float* ln_o_b = (const float*)d_in[14];
    const float* W_o    = (const float*)d_in[15];
    const float* b_o    = (const float*)d_in[16];
    const float* dw_o   = (const float*)d_in[17];
    float* out = (float*)d_out;

    unsigned char* pool;
    cudaGetSymbolAddress((void**)&pool, g_pool);
    float*         nx   = (float*)(pool + O_NX);
    __nv_bfloat16* lnH  = (__nv_bfloat16*)(pool + O_LNH);
    __nv_bfloat16* lnL  = (__nv_bfloat16*)(pool + O_LNL);
    __nv_bfloat16* whTH = (__nv_bfloat16*)(pool + O_WHTH);
    __nv_bfloat16* whTL = (__nv_bfloat16*)(pool + O_WHTL);
    __nv_bfloat16* wqTH = (__nv_bfloat16*)(pool + O_WQTH);
    __nv_bfloat16* wqTL = (__nv_bfloat16*)(pool + O_WQTL);
    __nv_bfloat16* woTH = (__nv_bfloat16*)(pool + O_WOTH);
    __nv_bfloat16* woTL = (__nv_bfloat16*)(pool + O_WOTL);
    float*         bufA = (float*)(pool + O_BUFA);
    float*         hid  = (float*)(pool + O_HID);
    __nv_bfloat16* hTH  = (__nv_bfloat16*)(pool + O_HTH);
    __nv_bfloat16* hTL  = (__nv_bfloat16*)(pool + O_HTL);
    float*         qk   = (float*)(pool + O_QK);
    float*         qk2  = (float*)(pool + O_QK2);
    __nv_bfloat16* qqH  = (__nv_bfloat16*)(pool + O_QQH);
    __nv_bfloat16* qqL  = (__nv_bfloat16*)(pool + O_QQL);
    __nv_bfloat16* lqH  = (__nv_bfloat16*)(pool + O_LQH);
    __nv_bfloat16* lqL  = (__nv_bfloat16*)(pool + O_LQL);
    __nv_bfloat16* qkH  = (__nv_bfloat16*)(pool + O_QKH);
    __nv_bfloat16* qkL  = (__nv_bfloat16*)(pool + O_QKL);
    float*         lkF  = (float*)(pool + O_LKF);
    __nv_bfloat16* lkTH = (__nv_bfloat16*)(pool + O_LKTH);
    __nv_bfloat16* lkTL = (__nv_bfloat16*)(pool + O_LKTL);
    __nv_bfloat16* attH = (__nv_bfloat16*)(pool + O_ATTH);
    __nv_bfloat16* attL = (__nv_bfloat16*)(pool + O_ATTL);
    float*         kvF  = (float*)(pool + O_KVF);
    __nv_bfloat16* kvH  = (__nv_bfloat16*)(pool + O_KVH);
    __nv_bfloat16* kvL  = (__nv_bfloat16*)(pool + O_KVL);
    float*         opre = nx;

    cudaFuncSetAttribute(gemm_k, cudaFuncAttributeMaxDynamicSharedMemorySize, GSMEM);

    // 1. token shift (float4)
    shift_k<<<(NT*(Dd/4) + 255)/256, 256>>>((const float4*)x, (float4*)nx);
    // 2. weight transposes -> bf16 hi/lo  [out,in] K-major
    trans_split_k<<<dim3(2048/32, 512/32, 1), 256>>>(W_h,  whTH, whTL, 512, 2048);
    trans_split_k<<<dim3(128/32,  512/32, 1), 256>>>(W_qk, wqTH, wqTL, 512, 128);
    trans_split_k<<<dim3(512/32, 1024/32, 1), 256>>>(W_o,  woTH, woTL, 1024, 512);
    // 3. LN_h -> hi/lo
    ln_split_k<<<NT, 256>>>(nx, ln_h_g, ln_h_b, lnH, lnL, Dd);
    // 4. GEMM1 -> bufA (SiLU)
    gemm_k<<<dim3(16, 128, 1), 256, GSMEM>>>(lnH, lnL, whTH, whTL, bufA, nullptr, nullptr,
        NT, HIDc, Dd, b_h, 1.f, F_SILU, 0, 0, 0);
    // 5. dwconv -> hid
    dwconv4_k<<<dim3(32, 16, Bb), 256>>>((const float4*)bufA, dw_h, nullptr,
                                         (float4*)hid, HIDc);
    // 6. hid per-group transpose -> hT [bg,2048,256]
    trans_split_k<<<dim3(64, 8, 64), 256>>>(hid, hTH, hTL, 256, 2048);
    // 7. LN_qk -> hi/lo
    ln_split_k<<<NT, 256>>>(nx, ln_qk_g, ln_qk_b, lnH, lnL, Dd);
    // 8. GEMM2 -> qk (SiLU)
    gemm_k<<<dim3(1, 128, 1), 256, GSMEM>>>(lnH, lnL, wqTH, wqTL, qk, nullptr, nullptr,
        NT, DQK, Dd, b_qk, 1.f, F_SILU, 0, 0, 0);
    // 9. dwconv -> qk2
    dwconv4_k<<<dim3(2, 16, Bb), 256>>>((const float4*)qk, dw_qk, nullptr,
                                        (float4*)qk2, DQK);
    // 10. offset-scale split
    qsplit_k<<<(NT*DQK/2 + 255)/256, 256>>>(qk2, gamma, beta, qqH, qqL, lqH, lqL, qkH, qkL, lkF);
    // 11. lin_k per-group transpose -> lkT [bg,128,256]
    trans_split_k<<<dim3(4, 8, 64), 256>>>(lkF, lkTH, lkTL, 256, 128);
    // 12. scores -> attH/attL (relu^2 causal, bf16 split)
    gemm_k<<<dim3(2, 2, 64), 256, GSMEM>>>(qqH, qqL, qkH, qkL, nullptr, attH, attL,
        GRP, GRP, DQK, nullptr, 1.f/GRP, F_SCORE,
        (long long)GRP*DQK, (long long)GRP*DQK, (long long)GRP*GRP);
    // 13. quad out: attn @ hidT^T -> bufA
    gemm_k<<<dim3(16, 2, 64), 256, GSMEM>>>(attH, attL, hTH, hTL, bufA, nullptr, nullptr,
        GRP, HIDc, GRP, nullptr, 1.f, 0,
        (long long)GRP*GRP, (long long)HIDc*GRP, (long long)GRP*HIDc);
    // 14. lin kv: lkT @ hidT^T / g -> kvF transposed [bg,2048,128]
    gemm_k<<<dim3(16, 1, 64), 256, GSMEM>>>(lkTH, lkTL, hTH, hTL, kvF, nullptr, nullptr,
        DQK, HIDc, GRP, nullptr, 1.f/GRP, F_TRC,
        (long long)DQK*GRP, (long long)HIDc*GRP, (long long)HIDc*DQK);
    // 15. exclusive group cumsum -> kvH/kvL
    cumsum_split_k<<<(int)(((size_t)Bb*2048*64 + 255)/256), 256>>>(kvF, kvH, kvL);
    // 16. lin out: lin_q @ kvT^T, accumulate into bufA
    gemm_k<<<dim3(16, 2, 64), 256, GSMEM>>>(lqH, lqL, kvH, kvL, bufA, nullptr, nullptr,
        GRP, HIDc, DQK, nullptr, 1.f, F_ACC,
        (long long)GRP*DQK, (long long)HIDc*DQK, (long long)GRP*HIDc);
    // 17. fused gating + LN_o -> lnH/lnL
    gate_ln_k<<<NT, 256>>>(bufA, hid, ln_o_g, ln_o_b, lnH, lnL);
    // 18. GEMM3 -> opre (SiLU)
    gemm_k<<<dim3(4, 128, 1), 256, GSMEM>>>(lnH, lnL, woTH, woTL, opre, nullptr, nullptr,
        NT, Dd, 2*Dd, b_o, 1.f, F_SILU, 0, 0, 0);
    // 19. dwconv + x residual -> out
    dwconv4_k<<<dim3(8, 16, Bb), 256>>>((const float4*)opre, dw_o, (const float4*)x,
                                        (float4*)out, Dd);
}

// round 8
// speedup vs baseline: 1.0367x; 1.0367x over previous
#include <cuda_runtime.h>
#include <cuda_bf16.h>
#include <cstdint>

#define Bb    8
#define Nn    2048
#define Dd    512
#define HIDc  2048
#define DQK   128
#define GRP   256
#define Gg    8
#define NT    (Bb*Nn)
#define Ee    1024
#define KK    17

// ================= warp MMA / async helpers (sm_80+ portable) =================
__device__ __forceinline__ uint32_t smem_to_u32(const void* p) {
    uint32_t a;
    asm("{ .reg .u64 t; cvta.to.shared.u64 t, %1; cvt.u32.u64 %0, t; }" : "=r"(a) : "l"(p));
    return a;
}
__device__ __forceinline__ void ldsm4(uint32_t* r, uint32_t addr) {
    asm volatile("ldmatrix.sync.aligned.m8n8.x4.shared.b16 {%0,%1,%2,%3}, [%4];"
        : "=r"(r[0]), "=r"(r[1]), "=r"(r[2]), "=r"(r[3]) : "r"(addr));
}
__device__ __forceinline__ void mma16816(float* c, const uint32_t* a, uint32_t b0, uint32_t b1) {
    asm volatile(
        "mma.sync.aligned.m16n8k16.row.col.f32.bf16.bf16.f32 "
        "{%0,%1,%2,%3}, {%4,%5,%6,%7}, {%8,%9}, {%0,%1,%2,%3};"
        : "+f"(c[0]), "+f"(c[1]), "+f"(c[2]), "+f"(c[3])
        : "r"(a[0]), "r"(a[1]), "r"(a[2]), "r"(a[3]), "r"(b0), "r"(b1));
}
__device__ __forceinline__ void cp16(uint32_t dst, const void* src) {
    asm volatile("cp.async.cg.shared.global [%0], [%1], 16;" :: "r"(dst), "l"(src));
}
#define CP_COMMIT() asm volatile("cp.async.commit_group;" ::: "memory")
#define CP_WAIT(N)  asm volatile("cp.async.wait_group %0;" :: "n"(N) : "memory")

#define F_SILU  1
#define F_ACC   2
#define F_SCORE 4
#define F_TRIA  16   // A block-lower-triangular in K: only K <= brow+128 contributes

// ================= scratch pool =================
#define SZF(n) ((size_t)(n)*4)
#define SZB(n) ((size_t)(n)*2)
static constexpr size_t O_NX   = 0;
static constexpr size_t O_LNH  = O_NX   + SZF((size_t)NT*512);
static constexpr size_t O_LNL  = O_LNH  + SZB((size_t)NT*1024);
static constexpr size_t O_WHTH = O_LNL  + SZB((size_t)NT*1024);
static constexpr size_t O_WHTL = O_WHTH + SZB(2048*512);
static constexpr size_t O_WQTH = O_WHTL + SZB(2048*512);
static constexpr size_t O_WQTL = O_WQTH + SZB(128*512);
static constexpr size_t O_WOTH = O_WQTL + SZB(128*512);
static constexpr size_t O_WOTL = O_WOTH + SZB(512*1024);
static constexpr size_t O_BUFA = O_WOTL + SZB(512*1024);
static constexpr size_t O_HID  = O_BUFA + SZF((size_t)NT*2048);
static constexpr size_t O_HTH  = O_HID  + SZF((size_t)NT*2048);
static constexpr size_t O_HTL  = O_HTH  + SZB((size_t)NT*2048);
static constexpr size_t O_QK   = O_HTL  + SZB((size_t)NT*2048);
static constexpr size_t O_QK2  = O_QK   + SZF((size_t)NT*128);
static constexpr size_t O_QQH  = O_QK2  + SZF((size_t)NT*128);
static constexpr size_t O_QQL  = O_QQH  + SZB((size_t)NT*128);
static constexpr size_t O_LQH  = O_QQL  + SZB((size_t)NT*128);
static constexpr size_t O_LQL  = O_LQH  + SZB((size_t)NT*128);
static constexpr size_t O_QKH  = O_LQL  + SZB((size_t)NT*128);
static constexpr size_t O_QKL  = O_QKH  + SZB((size_t)NT*128);
static constexpr size_t O_LKF  = O_QKL  + SZB((size_t)NT*128);
static constexpr size_t O_LKTH = O_LKF  + SZF((size_t)NT*128);
static constexpr size_t O_LKTL = O_LKTH + SZB((size_t)NT*128);
static constexpr size_t O_ATTH = O_LKTL + SZB((size_t)NT*128);
static constexpr size_t O_ATTL = O_ATTH + SZB((size_t)64*256*256);
static constexpr size_t O_KVF  = O_ATTL + SZB((size_t)64*256*256);
static constexpr size_t O_KVH  = O_KVF  + SZF((size_t)64*2048*128);
static constexpr size_t O_KVL  = O_KVH  + SZB((size_t)64*2048*128);
static constexpr size_t O_END  = O_KVL  + SZB((size_t)64*2048*128);
__device__ __align__(1024) unsigned char g_pool[O_END];

__device__ __forceinline__ void bsplit2(float v0, float v1, uint32_t& hu, uint32_t& lu) {
    __nv_bfloat16 h0 = __float2bfloat16(v0), h1 = __float2bfloat16(v1);
    __nv_bfloat16 l0 = __float2bfloat16(v0 - __bfloat162float(h0));
    __nv_bfloat16 l1 = __float2bfloat16(v1 - __bfloat162float(h1));
    hu = ((uint32_t)__bfloat16_as_ushort(h1) << 16) | __bfloat16_as_ushort(h0);
    lu = ((uint32_t)__bfloat16_as_ushort(l1) << 16) | __bfloat16_as_ushort(l0);
}

// ================= elementwise / prep kernels =================
__global__ void shift_k(const float4* __restrict__ x, float4* __restrict__ nx) {
    long i = (long)blockIdx.x * blockDim.x + threadIdx.x;
    if (i >= (long)NT*(Dd/4)) return;
    int c4 = (int)(i % (Dd/4));
    int n  = (int)((i / (Dd/4)) % Nn);
    if (c4 < Dd/8) nx[i] = (n == 0) ? make_float4(0,0,0,0) : x[i - Dd/4];
    else           nx[i] = x[i];
}

__global__ void ln_split_k(const float* __restrict__ in, const float* __restrict__ g,
                           const float* __restrict__ b,
                           __nv_bfloat16* __restrict__ oh, __nv_bfloat16* __restrict__ ol,
                           int C) {
    long row = blockIdx.x;
    const float2* xr2 = (const float2*)(in + row * C);
    int C2 = C >> 1;
    float s = 0.f, s2 = 0.f;
    for (int i = threadIdx.x; i < C2; i += blockDim.x) {
        float2 v = xr2[i]; s += v.x + v.y; s2 += v.x*v.x + v.y*v.y;
    }
    #pragma unroll
    for (int o = 16; o; o >>= 1) {
        s  += __shfl_xor_sync(~0u, s,  o);
        s2 += __shfl_xor_sync(~0u, s2, o);
    }
    __shared__ float shs[8], shs2[8], smu, sinv;
    int w = threadIdx.x >> 5, l = threadIdx.x & 31;
    if (l == 0) { shs[w] = s; shs2[w] = s2; }
    __syncthreads();
    if (threadIdx.x == 0) {
        float ts = 0.f, ts2 = 0.f;
        for (int i = 0; i < (int)(blockDim.x >> 5); i++) { ts += shs[i]; ts2 += shs2[i]; }
        float mu = ts / C;
        smu = mu; sinv = rsqrtf(ts2 / C - mu*mu + 1e-5f);
    }
    __syncthreads();
    float mu = smu, inv = sinv;
    uint32_t* oh2 = (uint32_t*)(oh + row*C);
    uint32_t* ol2 = (uint32_t*)(ol + row*C);
    const float2* g2 = (const float2*)g;
    const float2* b2 = (const float2*)b;
    for (int i = threadIdx.x; i < C2; i += blockDim.x) {
        float2 xv = xr2[i], gv = g2[i], bv = b2[i];
        float v0 = (xv.x - mu) * inv * gv.x + bv.x;
        float v1 = (xv.y - mu) * inv * gv.y + bv.y;
        uint32_t hu, lu;
        bsplit2(v0, v1, hu, lu);
        oh2[i] = hu; ol2[i] = lu;
    }
}

// fused gating + LN(1024) -> bf16 hi/lo
__global__ void gate_ln_k(const float* __restrict__ att, const float* __restrict__ hid,
                          const float* __restrict__ g, const float* __restrict__ b,
                          __nv_bfloat16* __restrict__ oh, __nv_bfloat16* __restrict__ ol) {
    long row = blockIdx.x;
    __shared__ float buf[1024];
    const float2* ar  = (const float2*)(att + row*HIDc);
    const float2* ar2 = (const float2*)(att + row*HIDc + Ee);
    const float2* hr  = (const float2*)(hid + row*HIDc);
    const float2* hr2 = (const float2*)(hid + row*HIDc + Ee);
    float s = 0.f, s2 = 0.f;
    for (int i = threadIdx.x; i < 512; i += blockDim.x) {
        float2 av = ar[i], au = ar2[i], v = hr[i], u = hr2[i];
        float t0 = au.x * v.x * (1.f / (1.f + expf(-(av.x * u.x))));
        float t1 = au.y * v.y * (1.f / (1.f + expf(-(av.y * u.y))));
        buf[2*i] = t0; buf[2*i+1] = t1;
        s += t0 + t1; s2 += t0*t0 + t1*t1;
    }
    #pragma unroll
    for (int o = 16; o; o >>= 1) {
        s  += __shfl_xor_sync(~0u, s,  o);
        s2 += __shfl_xor_sync(~0u, s2, o);
    }
    __shared__ float shs[8], shs2[8], smu, sinv;
    int w = threadIdx.x >> 5, l = threadIdx.x & 31;
    if (l == 0) { shs[w] = s; shs2[w] = s2; }
    __syncthreads();
    if (threadIdx.x == 0) {
        float ts = 0.f, ts2 = 0.f;
        for (int i = 0; i < (int)(blockDim.x >> 5); i++) { ts += shs[i]; ts2 += shs2[i]; }
        float mu = ts / 1024.f;
        smu = mu; sinv = rsqrtf(ts2 / 1024.f - mu*mu + 1e-5f);
    }
    __syncthreads();
    float mu = smu, inv = sinv;
    uint32_t* oh2 = (uint32_t*)(oh + row*1024);
    uint32_t* ol2 = (uint32_t*)(ol + row*1024);
    for (int i = threadIdx.x; i < 512; i += blockDim.x) {
        float v0 = (buf[2*i]   - mu) * inv * g[2*i]   + b[2*i];
        float v1 = (buf[2*i+1] - mu) * inv * g[2*i+1] + b[2*i+1];
        uint32_t hu, lu;
        bsplit2(v0, v1, hu, lu);
        oh2[i] = hu; ol2[i] = lu;
    }
}

// vectorized transpose fp32 [R,C] -> bf16 hi/lo [C,R], batched via blockIdx.z
__global__ void trans_split_k(const float* __restrict__ in,
                              __nv_bfloat16* __restrict__ oh, __nv_bfloat16* __restrict__ ol,
                              int R, int C) {
    __shared__ float s[32][36];
    size_t bz = (size_t)blockIdx.z * R * C;
    int c0 = blockIdx.x * 32, r0 = blockIdx.y * 32;
    int t = threadIdx.x;
    {
        int r = t >> 3, c4 = (t & 7) * 4;
        *(float4*)&s[r][c4] = *(const float4*)(in + bz + (size_t)(r0 + r)*C + c0 + c4);
    }
    __syncthreads();
    {
        int c = t & 31, rg = (t >> 5) * 4;
        float v0 = s[rg][c], v1 = s[rg+1][c], v2 = s[rg+2][c], v3 = s[rg+3][c];
        uint32_t h01, l01, h23, l23;
        bsplit2(v0, v1, h01, l01);
        bsplit2(v2, v3, h23, l23);
        size_t o = bz + (size_t)(c0 + c)*R + r0 + rg;
        *(uint2*)(oh + o) = make_uint2(h01, h23);
        *(uint2*)(ol + o) = make_uint2(l01, l23);
    }
}

// float4-vectorized depthwise conv K=17 + residual (+ optional extra residual)
__global__ void dwconv4_k(const float4* __restrict__ h4, const float* __restrict__ dw,
                          const float4* __restrict__ extra4, float4* __restrict__ out4, int C) {
    const int CT4 = 16, NTile = 128, HALO = 8;
    __shared__ float4 sh[NTile + 2*HALO][CT4];
    __shared__ float4 sdw[KK][CT4];
    int b = blockIdx.z, n0 = blockIdx.y * NTile, c0 = blockIdx.x * CT4;
    int C4 = C >> 2;
    const float4* base = h4 + (size_t)b*Nn*C4 + c0;
    for (int idx = threadIdx.x; idx < (NTile + 2*HALO)*CT4; idx += blockDim.x) {
        int r = idx >> 4, c = idx & 15;
        int n = n0 - HALO + r;
        sh[r][c] = (n >= 0 && n < Nn) ? base[(size_t)n*C4 + c] : make_float4(0,0,0,0);
    }
    for (int idx = threadIdx.x; idx < KK*CT4; idx += blockDim.x) {
        int k = idx >> 4, c = idx & 15;
        const float* w = dw + k*C + (c0 + c)*4;
        sdw[k][c] = make_float4(w[0], w[1], w[2], w[3]);
    }
    __syncthreads();
    for (int idx = threadIdx.x; idx < NTile*CT4; idx += blockDim.x) {
        int r = idx >> 4, c = idx & 15;
        float4 acc = sh[r + HALO][c];
        #pragma unroll
        for (int k = 0; k < KK; k++) {
            float4 a = sh[r + k][c], w = sdw[k][c];
            acc.x += a.x*w.x; acc.y += a.y*w.y; acc.z += a.z*w.z; acc.w += a.w*w.w;
        }
        size_t o = (size_t)b*Nn*C4 + (size_t)(n0 + r)*C4 + c0 + c;
        if (extra4) {
            float4 e = extra4[o];
            acc.x += e.x; acc.y += e.y; acc.z += e.z; acc.w += e.w;
        }
        out4[o] = acc;
    }
}

__global__ void qsplit_k(const float* __restrict__ qk, const float* __restrict__ gamma,
                         const float* __restrict__ beta,
                         __nv_bfloat16* qqh, __nv_bfloat16* qql,
                         __nv_bfloat16* lqh, __nv_bfloat16* lql,
                         __nv_bfloat16* qkh, __nv_bfloat16* qkl,
                         float* lkf) {
    long i2 = (long)blockIdx.x * blockDim.x + threadIdx.x;      // over NT*DQK/2
    if (i2 >= (long)NT*DQK/2) return;
    int d = (int)((i2 & 63) * 2);
    float2 v = ((const float2*)qk)[i2];
    uint32_t hu, lu;
    float a0, a1;
    a0 = v.x * gamma[0*DQK + d] + beta[0*DQK + d];
    a1 = v.y * gamma[0*DQK + d+1] + beta[0*DQK + d+1];
    bsplit2(a0, a1, hu, lu);
    ((uint32_t*)qqh)[i2] = hu; ((uint32_t*)qql)[i2] = lu;
    a0 = v.x * gamma[1*DQK + d] + beta[1*DQK + d];
    a1 = v.y * gamma[1*DQK + d+1] + beta[1*DQK + d+1];
    bsplit2(a0, a1, hu, lu);
    ((uint32_t*)lqh)[i2] = hu; ((uint32_t*)lql)[i2] = lu;
    a0 = v.x * gamma[2*DQK + d] + beta[2*DQK + d];
    a1 = v.y * gamma[2*DQK + d+1] + beta[2*DQK + d+1];
    bsplit2(a0, a1, hu, lu);
    ((uint32_t*)qkh)[i2] = hu; ((uint32_t*)qkl)[i2] = lu;
    float2 lk;
    lk.x = v.x * gamma[3*DQK + d] + beta[3*DQK + d];
    lk.y = v.y * gamma[3*DQK + d+1] + beta[3*DQK + d+1];
    ((float2*)lkf)[i2] = lk;
}

__global__ void cumsum_split_k(const float* __restrict__ kvf,
                               __nv_bfloat16* __restrict__ oh,
                               __nv_bfloat16* __restrict__ ol) {
    const size_t S = (size_t)2048*128;
    long i2 = (long)blockIdx.x * blockDim.x + threadIdx.x;      // over Bb*S/2
    if (i2 >= (long)Bb*(S/2)) return;
    size_t b = (size_t)i2 / (S/2), r2 = (size_t)i2 % (S/2);
    size_t base2 = b*Gg*(S/2) + r2;
    float s0 = 0.f, s1 = 0.f;
    #pragma unroll
    for (int g = 0; g < Gg; g++) {
        size_t o2 = base2 + (size_t)g*(S/2);
        float2 v = ((const float2*)kvf)[o2];
        uint32_t hu, lu;
        bsplit2(s0, s1, hu, lu);
        ((uint32_t*)oh)[o2] = hu; ((uint32_t*)ol)[o2] = lu;
        s0 += v.x; s1 += v.y;
    }
}

// ================= HMMA bf16x3 GEMM — fused hi/lo staging, 2-stage pipeline ======
// Stage row layout (144 B): cols 0-31 = hi chunk, cols 32-63 = lo chunk (K-chunk = 32).
#define LDA 72            // bf16 elems per smem row (64 data + 8 pad) = 144 B
#define STG_BYTES 36864   // one stage: A (18432) + B (18432)
#define GSMEM (2*STG_BYTES)

__global__ void __launch_bounds__(256, 2) gemm_k(
    const __nv_bfloat16* __restrict__ Ah, const __nv_bfloat16* __restrict__ Al,
    const __nv_bfloat16* __restrict__ Bh, const __nv_bfloat16* __restrict__ Bl,
    float* C, __nv_bfloat16* Ch, __nv_bfloat16* Cl,
    int M, int N, int Ktot, const float* __restrict__ bias, float alpha, int flags,
    long long sA, long long sB, long long sC)
{
    extern __shared__ __align__(16) unsigned char smem[];
    uint32_t sbase = smem_to_u32(smem);
    int tid = threadIdx.x, lane = tid & 31, wid = tid >> 5;
    int wm = wid & 3, wn = wid >> 2;            // 4 (M) x 2 (N) warps
    int brow = blockIdx.y * 128, bcol = blockIdx.x * 128;
    long long bz = blockIdx.z;
    Ah += bz*sA; Al += bz*sA; Bh += bz*sB; Bl += bz*sB;
    if (C)  C  += bz*sC;
    if (Ch) { Ch += bz*sC; Cl += bz*sC; }

    // fully-masked score tile: zero-fill and exit
    if ((flags & F_SCORE) && bcol > brow) {
        uint4 z = make_uint4(0,0,0,0);
        for (int e = tid; e < 2048; e += 256) {
            int row = e >> 4, seg = e & 15;
            *(uint4*)(Ch + (size_t)(brow + row)*N + bcol + seg*8) = z;
            *(uint4*)(Cl + (size_t)(brow + row)*N + bcol + seg*8) = z;
        }
        return;
    }

    float acc[2][8][4];
    #pragma unroll
    for (int i = 0; i < 2; i++)
        #pragma unroll
        for (int j = 0; j < 8; j++)
            #pragma unroll
            for (int q = 0; q < 4; q++) acc[i][j][q] = 0.f;

    uint32_t aOff = (uint32_t)(((wm*32 + (lane & 15)) * LDA + (lane >> 4)*8) * 2);
    uint32_t bOff = (uint32_t)(((wn*64 + ((lane >> 4) & 1)*8 + (lane & 7)) * LDA
                                + ((lane >> 3) & 1)*8) * 2) + 18432;
    const int ldr = tid >> 3, lds2 = tid & 7;
    const int seg = lds2 & 3;

    int KC = Ktot >> 5;                         // 32-K chunks (hi+lo staged together)
    if (flags & F_TRIA) {                       // only K <= brow+128 contributes
        int kc2 = (brow + 128) >> 5;
        if (kc2 < KC) KC = kc2;
    }

    auto issue = [&](int it) {
        int k0 = it << 5;
        const __nv_bfloat16* As = (lds2 < 4) ? Ah : Al;
        const __nv_bfloat16* Bs = (lds2 < 4) ? Bh : Bl;
        uint32_t sa = sbase + (uint32_t)(it & 1)*STG_BYTES;
        #pragma unroll
        for (int e = 0; e < 4; e++) {
            int r = ldr + e*32;
            cp16(sa + (uint32_t)(r*144 + lds2*16),
                 As + (size_t)(brow + r)*Ktot + k0 + seg*8);
            cp16(sa + 18432u + (uint32_t)(r*144 + lds2*16),
                 Bs + (size_t)(bcol + r)*Ktot + k0 + seg*8);
        }
        CP_COMMIT();
    };

    issue(0);
    for (int it = 0; it < KC; ++it) {
        if (it + 1 < KC) { issue(it + 1); CP_WAIT(1); }
        else             { CP_WAIT(0); }
        __syncthreads();
        uint32_t stg = sbase + (uint32_t)(it & 1)*STG_BYTES;
        uint32_t aB = stg + aOff, bB = stg + bOff;
        #pragma unroll
        for (int kk = 0; kk < 2; kk++) {
            uint32_t afh[2][4], afl[2][4];
            #pragma unroll
            for (int i = 0; i < 2; i++) {
                ldsm4(afh[i], aB + (uint32_t)((i*16*LDA + kk*16) * 2));
                ldsm4(afl[i], aB + (uint32_t)((i*16*LDA + 32 + kk*16) * 2));
            }
            #pragma unroll
            for (int p = 0; p < 4; p++) {
                uint32_t bh[4], bl[4];
                ldsm4(bh, bB + (uint32_t)((p*16*LDA + kk*16) * 2));
                ldsm4(bl, bB + (uint32_t)((p*16*LDA + 32 + kk*16) * 2));
                #pragma unroll
                for (int i = 0; i < 2; i++) {
                    mma16816(acc[i][2*p],   afh[i], bh[0], bh[1]);
                    mma16816(acc[i][2*p+1], afh[i], bh[2], bh[3]);
                    mma16816(acc[i][2*p],   afl[i], bh[0], bh[1]);
                    mma16816(acc[i][2*p+1], afl[i], bh[2], bh[3]);
                    mma16816(acc[i][2*p],   afh[i], bl[0], bl[1]);
                    mma16816(acc[i][2*p+1], afh[i], bl[2], bl[3]);
                }
            }
        }
        __syncthreads();
    }

    // ---- epilogue ----
    int g = lane >> 2, c2 = (lane & 3)*2;
    #pragma unroll
    for (int i = 0; i < 2; i++) {
        #pragma unroll
        for (int j = 0; j < 8; j++) {
            #pragma unroll
            for (int rr = 0; rr < 2; rr++) {
                int row = brow + wm*32 + i*16 + g + rr*8;
                int col = bcol + wn*64 + j*8 + c2;
                float v0 = acc[i][j][rr*2+0] * alpha;
                float v1 = acc[i][j][rr*2+1] * alpha;
                if (flags & F_SCORE) {
                    v0 = fmaxf(v0, 0.f); v0 *= v0;
                    v1 = fmaxf(v1, 0.f); v1 *= v1;
                    if (col     > row) v0 = 0.f;
                    if (col + 1 > row) v1 = 0.f;
                    size_t o = (size_t)row*N + col;
                    uint32_t hu, lu;
                    bsplit2(v0, v1, hu, lu);
                    *(uint32_t*)(Ch + o) = hu;
                    *(uint32_t*)(Cl + o) = lu;
                } else {
                    if (bias) { v0 += bias[col]; v1 += bias[col+1]; }
                    if (flags & F_SILU) {
                        v0 = v0 / (1.f + expf(-v0));
                        v1 = v1 / (1.f + expf(-v1));
                    }
                    size_t o = (size_t)row*N + col;
                    if (flags & F_ACC) { v0 += C[o]; v1 += C[o+1]; }
                    *(float2*)(C + o) = make_float2(v0, v1);
                }
            }
        }
    }
}

// ================= launcher =================
extern "C" void kernel_launch(void* const* d_in, const int* in_sizes, int n_in,
                              void* d_out, int out_size) {
    const float* x      = (const float*)d_in[0];
    const float* ln_h_g = (const float*)d_in[1];
    const float* ln_h_b = (const float*)d_in[2];
    const float* W_h    = (const float*)d_in[3];
    const float* b_h    = (const float*)d_in[4];
    const float* dw_h   = (const float*)d_in[5];
    const float* ln_qk_g= (const float*)d_in[6];
    const float* ln_qk_b= (const float*)d_in[7];
    const float* W_qk   = (const float*)d_in[8];
    const float* b_qk   = (const float*)d_in[9];
    const float* dw_qk  = (const float*)d_in[10];
    const float* gamma  = (const float*)d_in[11];
    const float* beta   = (const float*)d_in[12];
    const float* ln_o_g = (const float*)d_in[13];
    const float* ln_o_b = (const float*)d_in[14];
    const float* W_o    = (const float*)d_in[15];
    const float* b_o    = (const float*)d_in[16];
    const float* dw_o   = (const float*)d_in[17];
    float* out = (float*)d_out;

    unsigned char* pool;
    cudaGetSymbolAddress((void**)&pool, g_pool);
    float*         nx   = (float*)(pool + O_NX);
    __nv_bfloat16* lnH  = (__nv_bfloat16*)(pool + O_LNH);
    __nv_bfloat16* lnL  = (__nv_bfloat16*)(pool + O_LNL);
    __nv_bfloat16* whTH = (__nv_bfloat16*)(pool + O_WHTH);
    __nv_bfloat16* whTL = (__nv_bfloat16*)(pool + O_WHTL);
    __nv_bfloat16* wqTH = (__nv_bfloat16*)(pool + O_WQTH);
    __nv_bfloat16* wqTL = (__nv_bfloat16*)(pool + O_WQTL);
    __nv_bfloat16* woTH = (__nv_bfloat16*)(pool + O_WOTH);
    __nv_bfloat16* woTL = (__nv_bfloat16*)(pool + O_WOTL);
    float*         bufA = (float*)(pool + O_BUFA);
    float*         hid  = (float*)(pool + O_HID);
    __nv_bfloat16* hTH  = (__nv_bfloat16*)(pool + O_HTH);
    __nv_bfloat16* hTL  = (__nv_bfloat16*)(pool + O_HTL);
    float*         qk   = (float*)(pool + O_QK);
    float*         qk2  = (float*)(pool + O_QK2);
    __nv_bfloat16* qqH  = (__nv_bfloat16*)(pool + O_QQH);
    __nv_bfloat16* qqL  = (__nv_bfloat16*)(pool + O_QQL);
    __nv_bfloat16* lqH  = (__nv_bfloat16*)(pool + O_LQH);
    __nv_bfloat16* lqL  = (__nv_bfloat16*)(pool + O_LQL);
    __nv_bfloat16* qkH  = (__nv_bfloat16*)(pool + O_QKH);
    __nv_bfloat16* qkL  = (__nv_bfloat16*)(pool + O_QKL);
    float*         lkF  = (float*)(pool + O_LKF);
    __nv_bfloat16* lkTH = (__nv_bfloat16*)(pool + O_LKTH);
    __nv_bfloat16* lkTL = (__nv_bfloat16*)(pool + O_LKTL);
    __nv_bfloat16* attH = (__nv_bfloat16*)(pool + O_ATTH);
    __nv_bfloat16* attL = (__nv_bfloat16*)(pool + O_ATTL);
    float*         kvF  = (float*)(pool + O_KVF);
    __nv_bfloat16* kvH  = (__nv_bfloat16*)(pool + O_KVH);
    __nv_bfloat16* kvL  = (__nv_bfloat16*)(pool + O_KVL);
    float*         opre = nx;

    cudaFuncSetAttribute(gemm_k, cudaFuncAttributeMaxDynamicSharedMemorySize, GSMEM);

    // 1. token shift (float4)
    shift_k<<<(NT*(Dd/4) + 255)/256, 256>>>((const float4*)x, (float4*)nx);
    // 2. weight transposes -> bf16 hi/lo  [out,in] K-major
    trans_split_k<<<dim3(2048/32, 512/32, 1), 256>>>(W_h,  whTH, whTL, 512, 2048);
    trans_split_k<<<dim3(128/32,  512/32, 1), 256>>>(W_qk, wqTH, wqTL, 512, 128);
    trans_split_k<<<dim3(512/32, 1024/32, 1), 256>>>(W_o,  woTH, woTL, 1024, 512);
    // 3. LN_h -> hi/lo
    ln_split_k<<<NT, 256>>>(nx, ln_h_g, ln_h_b, lnH, lnL, Dd);
    // 4. GEMM1 -> bufA (SiLU)
    gemm_k<<<dim3(16, 128, 1), 256, GSMEM>>>(lnH, lnL, whTH, whTL, bufA, nullptr, nullptr,
        NT, HIDc, Dd, b_h, 1.f, F_SILU, 0, 0, 0);
    // 5. dwconv -> hid
    dwconv4_k<<<dim3(32, 16, Bb), 256>>>((const float4*)bufA, dw_h, nullptr,
                                         (float4*)hid, HIDc);
    // 6. hid per-group transpose -> hT [bg,2048,256]
    trans_split_k<<<dim3(64, 8, 64), 256>>>(hid, hTH, hTL, 256, 2048);
    // 7. LN_qk -> hi/lo
    ln_split_k<<<NT, 256>>>(nx, ln_qk_g, ln_qk_b, lnH, lnL, Dd);
    // 8. GEMM2 -> qk (SiLU)
    gemm_k<<<dim3(1, 128, 1), 256, GSMEM>>>(lnH, lnL, wqTH, wqTL, qk, nullptr, nullptr,
        NT, DQK, Dd, b_qk, 1.f, F_SILU, 0, 0, 0);
    // 9. dwconv -> qk2
    dwconv4_k<<<dim3(2, 16, Bb), 256>>>((const float4*)qk, dw_qk, nullptr,
                                        (float4*)qk2, DQK);
    // 10. offset-scale split
    qsplit_k<<<(NT*DQK/2 + 255)/256, 256>>>(qk2, gamma, beta, qqH, qqL, lqH, lqL, qkH, qkL, lkF);
    // 11. lin_k per-group transpose -> lkT [bg,128,256]
    trans_split_k<<<dim3(4, 8, 64), 256>>>(lkF, lkTH, lkTL, 256, 128);
    // 12. scores -> attH/attL (relu^2 causal, bf16 split)
    gemm_k<<<dim3(2, 2, 64), 256, GSMEM>>>(qqH, qqL, qkH, qkL, nullptr, attH, attL,
        GRP, GRP, DQK, nullptr, 1.f/GRP, F_SCORE,
        (long long)GRP*DQK, (long long)GRP*DQK, (long long)GRP*GRP);
    // 13. quad out: attn @ hidT^T -> bufA (triangular K-skip)
    gemm_k<<<dim3(16, 2, 64), 256, GSMEM>>>(attH, attL, hTH, hTL, bufA, nullptr, nullptr,
        GRP, HIDc, GRP, nullptr, 1.f, F_TRIA,
        (long long)GRP*GRP, (long long)HIDc*GRP, (long long)GRP*HIDc);
    // 14. lin kv (operand-swapped, coalesced): out[e,d] = sum_n hT[e,n]*lkT[d,n] / g
    //     -> kvF [bg, 2048(e), 128(d)] row-major == kv^T layout
    gemm_k<<<dim3(1, 16, 64), 256, GSMEM>>>(hTH, hTL, lkTH, lkTL, kvF, nullptr, nullptr,
        HIDc, DQK, GRP, nullptr, 1.f/GRP, 0,
        (long long)HIDc*GRP, (long long)DQK*GRP, (long long)HIDc*DQK);
    // 15. exclusive group cumsum -> kvH/kvL
    cumsum_split_k<<<(int)(((size_t)Bb*2048*64 + 255)/256), 256>>>(kvF, kvH, kvL);
    // 16. lin out: lin_q @ kvT^T, accumulate into bufA
    gemm_k<<<dim3(16, 2, 64), 256, GSMEM>>>(lqH, lqL, kvH, kvL, bufA, nullptr, nullptr,
        GRP, HIDc, DQK, nullptr, 1.f, F_ACC,
        (long long)GRP*DQK, (long long)HIDc*DQK, (long long)GRP*HIDc);
    // 17. fused gating + LN_o -> lnH/lnL
    gate_ln_k<<<NT, 256>>>(bufA, hid, ln_o_g, ln_o_b, lnH, lnL);
    // 18. GEMM3 -> opre (SiLU)
    gemm_k<<<dim3(4, 128, 1), 256, GSMEM>>>(lnH, lnL, woTH, woTL, opre, nullptr, nullptr,
        NT, Dd, 2*Dd, b_o, 1.f, F_SILU, 0, 0, 0);
    // 19. dwconv + x residual -> out
    dwconv4_k<<<dim3(8, 16, Bb), 256>>>((const float4*)opre, dw_o, (const float4*)x,
                                        (float4*)out, Dd);
}

// round 9
// speedup vs baseline: 1.1858x; 1.1438x over previous
#include <cuda_runtime.h>
#include <cuda_bf16.h>
#include <cstdint>

#define Bb    8
#define Nn    2048
#define Dd    512
#define HIDc  2048
#define DQK   128
#define GRP   256
#define Gg    8
#define NT    (Bb*Nn)
#define Ee    1024
#define KK    17

// ================= warp MMA / async helpers (sm_80+ portable) =================
__device__ __forceinline__ uint32_t smem_to_u32(const void* p) {
    uint32_t a;
    asm("{ .reg .u64 t; cvta.to.shared.u64 t, %1; cvt.u32.u64 %0, t; }" : "=r"(a) : "l"(p));
    return a;
}
__device__ __forceinline__ void ldsm4(uint32_t* r, uint32_t addr) {
    asm volatile("ldmatrix.sync.aligned.m8n8.x4.shared.b16 {%0,%1,%2,%3}, [%4];"
        : "=r"(r[0]), "=r"(r[1]), "=r"(r[2]), "=r"(r[3]) : "r"(addr));
}
__device__ __forceinline__ void mma16816(float* c, const uint32_t* a, uint32_t b0, uint32_t b1) {
    asm volatile(
        "mma.sync.aligned.m16n8k16.row.col.f32.bf16.bf16.f32 "
        "{%0,%1,%2,%3}, {%4,%5,%6,%7}, {%8,%9}, {%0,%1,%2,%3};"
        : "+f"(c[0]), "+f"(c[1]), "+f"(c[2]), "+f"(c[3])
        : "r"(a[0]), "r"(a[1]), "r"(a[2]), "r"(a[3]), "r"(b0), "r"(b1));
}
__device__ __forceinline__ void cp16(uint32_t dst, const void* src) {
    asm volatile("cp.async.cg.shared.global [%0], [%1], 16;" :: "r"(dst), "l"(src));
}
#define CP_COMMIT() asm volatile("cp.async.commit_group;" ::: "memory")
#define CP_WAIT(N)  asm volatile("cp.async.wait_group %0;" :: "n"(N) : "memory")

#define F_SILU  1
#define F_ACC   2
#define F_SCORE 4
#define F_TRIA  16   // A block-lower-triangular in K: only K <= brow+128 contributes

// ================= scratch pool =================
#define SZF(n) ((size_t)(n)*4)
#define SZB(n) ((size_t)(n)*2)
static constexpr size_t O_NX   = 0;
static constexpr size_t O_LNH  = O_NX   + SZF((size_t)NT*512);
static constexpr size_t O_LNL  = O_LNH  + SZB((size_t)NT*1024);
static constexpr size_t O_WHTH = O_LNL  + SZB((size_t)NT*1024);
static constexpr size_t O_WHTL = O_WHTH + SZB(2048*512);
static constexpr size_t O_WQTH = O_WHTL + SZB(2048*512);
static constexpr size_t O_WQTL = O_WQTH + SZB(128*512);
static constexpr size_t O_WOTH = O_WQTL + SZB(128*512);
static constexpr size_t O_WOTL = O_WOTH + SZB(512*1024);
static constexpr size_t O_BUFA = O_WOTL + SZB(512*1024);
static constexpr size_t O_HID  = O_BUFA + SZF((size_t)NT*2048);
static constexpr size_t O_HTH  = O_HID  + SZF((size_t)NT*2048);
static constexpr size_t O_HTL  = O_HTH  + SZB((size_t)NT*2048);
static constexpr size_t O_QK   = O_HTL  + SZB((size_t)NT*2048);
static constexpr size_t O_QK2  = O_QK   + SZF((size_t)NT*128);
static constexpr size_t O_QQH  = O_QK2  + SZF((size_t)NT*128);
static constexpr size_t O_QQL  = O_QQH  + SZB((size_t)NT*128);
static constexpr size_t O_LQH  = O_QQL  + SZB((size_t)NT*128);
static constexpr size_t O_LQL  = O_LQH  + SZB((size_t)NT*128);
static constexpr size_t O_QKH  = O_LQL  + SZB((size_t)NT*128);
static constexpr size_t O_QKL  = O_QKH  + SZB((size_t)NT*128);
static constexpr size_t O_LKF  = O_QKL  + SZB((size_t)NT*128);
static constexpr size_t O_LKTH = O_LKF  + SZF((size_t)NT*128);
static constexpr size_t O_LKTL = O_LKTH + SZB((size_t)NT*128);
static constexpr size_t O_ATTH = O_LKTL + SZB((size_t)NT*128);
static constexpr size_t O_ATTL = O_ATTH + SZB((size_t)64*256*256);
static constexpr size_t O_KVF  = O_ATTL + SZB((size_t)64*256*256);
static constexpr size_t O_KVH  = O_KVF  + SZF((size_t)64*2048*128);
static constexpr size_t O_KVL  = O_KVH  + SZB((size_t)64*2048*128);
static constexpr size_t O_END  = O_KVL  + SZB((size_t)64*2048*128);
__device__ __align__(1024) unsigned char g_pool[O_END];

__device__ __forceinline__ void bsplit2(float v0, float v1, uint32_t& hu, uint32_t& lu) {
    __nv_bfloat16 h0 = __float2bfloat16(v0), h1 = __float2bfloat16(v1);
    __nv_bfloat16 l0 = __float2bfloat16(v0 - __bfloat162float(h0));
    __nv_bfloat16 l1 = __float2bfloat16(v1 - __bfloat162float(h1));
    hu = ((uint32_t)__bfloat16_as_ushort(h1) << 16) | __bfloat16_as_ushort(h0);
    lu = ((uint32_t)__bfloat16_as_ushort(l1) << 16) | __bfloat16_as_ushort(l0);
}

// ================= elementwise / prep kernels =================
__global__ void shift_k(const float4* __restrict__ x, float4* __restrict__ nx) {
    long i = (long)blockIdx.x * blockDim.x + threadIdx.x;
    if (i >= (long)NT*(Dd/4)) return;
    int c4 = (int)(i % (Dd/4));
    int n  = (int)((i / (Dd/4)) % Nn);
    if (c4 < Dd/8) nx[i] = (n == 0) ? make_float4(0,0,0,0) : x[i - Dd/4];
    else           nx[i] = x[i];
}

__global__ void ln_split_k(const float* __restrict__ in, const float* __restrict__ g,
                           const float* __restrict__ b,
                           __nv_bfloat16* __restrict__ oh, __nv_bfloat16* __restrict__ ol,
                           int C) {
    long row = blockIdx.x;
    const float2* xr2 = (const float2*)(in + row * C);
    int C2 = C >> 1;
    float s = 0.f, s2 = 0.f;
    for (int i = threadIdx.x; i < C2; i += blockDim.x) {
        float2 v = xr2[i]; s += v.x + v.y; s2 += v.x*v.x + v.y*v.y;
    }
    #pragma unroll
    for (int o = 16; o; o >>= 1) {
        s  += __shfl_xor_sync(~0u, s,  o);
        s2 += __shfl_xor_sync(~0u, s2, o);
    }
    __shared__ float shs[8], shs2[8], smu, sinv;
    int w = threadIdx.x >> 5, l = threadIdx.x & 31;
    if (l == 0) { shs[w] = s; shs2[w] = s2; }
    __syncthreads();
    if (threadIdx.x == 0) {
        float ts = 0.f, ts2 = 0.f;
        for (int i = 0; i < (int)(blockDim.x >> 5); i++) { ts += shs[i]; ts2 += shs2[i]; }
        float mu = ts / C;
        smu = mu; sinv = rsqrtf(ts2 / C - mu*mu + 1e-5f);
    }
    __syncthreads();
    float mu = smu, inv = sinv;
    uint32_t* oh2 = (uint32_t*)(oh + row*C);
    uint32_t* ol2 = (uint32_t*)(ol + row*C);
    const float2* g2 = (const float2*)g;
    const float2* b2 = (const float2*)b;
    for (int i = threadIdx.x; i < C2; i += blockDim.x) {
        float2 xv = xr2[i], gv = g2[i], bv = b2[i];
        float v0 = (xv.x - mu) * inv * gv.x + bv.x;
        float v1 = (xv.y - mu) * inv * gv.y + bv.y;
        uint32_t hu, lu;
        bsplit2(v0, v1, hu, lu);
        oh2[i] = hu; ol2[i] = lu;
    }
}

// fused gating + LN(1024) -> bf16 hi/lo
__global__ void gate_ln_k(const float* __restrict__ att, const float* __restrict__ hid,
                          const float* __restrict__ g, const float* __restrict__ b,
                          __nv_bfloat16* __restrict__ oh, __nv_bfloat16* __restrict__ ol) {
    long row = blockIdx.x;
    __shared__ float buf[1024];
    const float2* ar  = (const float2*)(att + row*HIDc);
    const float2* ar2 = (const float2*)(att + row*HIDc + Ee);
    const float2* hr  = (const float2*)(hid + row*HIDc);
    const float2* hr2 = (const float2*)(hid + row*HIDc + Ee);
    float s = 0.f, s2 = 0.f;
    for (int i = threadIdx.x; i < 512; i += blockDim.x) {
        float2 av = ar[i], au = ar2[i], v = hr[i], u = hr2[i];
        float t0 = au.x * v.x * (1.f / (1.f + expf(-(av.x * u.x))));
        float t1 = au.y * v.y * (1.f / (1.f + expf(-(av.y * u.y))));
        buf[2*i] = t0; buf[2*i+1] = t1;
        s += t0 + t1; s2 += t0*t0 + t1*t1;
    }
    #pragma unroll
    for (int o = 16; o; o >>= 1) {
        s  += __shfl_xor_sync(~0u, s,  o);
        s2 += __shfl_xor_sync(~0u, s2, o);
    }
    __shared__ float shs[8], shs2[8], smu, sinv;
    int w = threadIdx.x >> 5, l = threadIdx.x & 31;
    if (l == 0) { shs[w] = s; shs2[w] = s2; }
    __syncthreads();
    if (threadIdx.x == 0) {
        float ts = 0.f, ts2 = 0.f;
        for (int i = 0; i < (int)(blockDim.x >> 5); i++) { ts += shs[i]; ts2 += shs2[i]; }
        float mu = ts / 1024.f;
        smu = mu; sinv = rsqrtf(ts2 / 1024.f - mu*mu + 1e-5f);
    }
    __syncthreads();
    float mu = smu, inv = sinv;
    uint32_t* oh2 = (uint32_t*)(oh + row*1024);
    uint32_t* ol2 = (uint32_t*)(ol + row*1024);
    for (int i = threadIdx.x; i < 512; i += blockDim.x) {
        float v0 = (buf[2*i]   - mu) * inv * g[2*i]   + b[2*i];
        float v1 = (buf[2*i+1] - mu) * inv * g[2*i+1] + b[2*i+1];
        uint32_t hu, lu;
        bsplit2(v0, v1, hu, lu);
        oh2[i] = hu; ol2[i] = lu;
    }
}

// vectorized transpose fp32 [R,C] -> bf16 hi/lo [C,R], batched via blockIdx.z
__global__ void trans_split_k(const float* __restrict__ in,
                              __nv_bfloat16* __restrict__ oh, __nv_bfloat16* __restrict__ ol,
                              int R, int C) {
    __shared__ float s[32][36];
    size_t bz = (size_t)blockIdx.z * R * C;
    int c0 = blockIdx.x * 32, r0 = blockIdx.y * 32;
    int t = threadIdx.x;
    {
        int r = t >> 3, c4 = (t & 7) * 4;
        *(float4*)&s[r][c4] = *(const float4*)(in + bz + (size_t)(r0 + r)*C + c0 + c4);
    }
    __syncthreads();
    {
        int c = t & 31, rg = (t >> 5) * 4;
        float v0 = s[rg][c], v1 = s[rg+1][c], v2 = s[rg+2][c], v3 = s[rg+3][c];
        uint32_t h01, l01, h23, l23;
        bsplit2(v0, v1, h01, l01);
        bsplit2(v2, v3, h23, l23);
        size_t o = bz + (size_t)(c0 + c)*R + r0 + rg;
        *(uint2*)(oh + o) = make_uint2(h01, h23);
        *(uint2*)(ol + o) = make_uint2(l01, l23);
    }
}

// float4-vectorized depthwise conv K=17 + residual (+ optional extra residual)
__global__ void dwconv4_k(const float4* __restrict__ h4, const float* __restrict__ dw,
                          const float4* __restrict__ extra4, float4* __restrict__ out4, int C) {
    const int CT4 = 16, NTile = 128, HALO = 8;
    __shared__ float4 sh[NTile + 2*HALO][CT4];
    __shared__ float4 sdw[KK][CT4];
    int b = blockIdx.z, n0 = blockIdx.y * NTile, c0 = blockIdx.x * CT4;
    int C4 = C >> 2;
    const float4* base = h4 + (size_t)b*Nn*C4 + c0;
    for (int idx = threadIdx.x; idx < (NTile + 2*HALO)*CT4; idx += blockDim.x) {
        int r = idx >> 4, c = idx & 15;
        int n = n0 - HALO + r;
        sh[r][c] = (n >= 0 && n < Nn) ? base[(size_t)n*C4 + c] : make_float4(0,0,0,0);
    }
    for (int idx = threadIdx.x; idx < KK*CT4; idx += blockDim.x) {
        int k = idx >> 4, c = idx & 15;
        const float* w = dw + k*C + (c0 + c)*4;
        sdw[k][c] = make_float4(w[0], w[1], w[2], w[3]);
    }
    __syncthreads();
    for (int idx = threadIdx.x; idx < NTile*CT4; idx += blockDim.x) {
        int r = idx >> 4, c = idx & 15;
        float4 acc = sh[r + HALO][c];
        #pragma unroll
        for (int k = 0; k < KK; k++) {
            float4 a = sh[r + k][c], w = sdw[k][c];
            acc.x += a.x*w.x; acc.y += a.y*w.y; acc.z += a.z*w.z; acc.w += a.w*w.w;
        }
        size_t o = (size_t)b*Nn*C4 + (size_t)(n0 + r)*C4 + c0 + c;
        if (extra4) {
            float4 e = extra4[o];
            acc.x += e.x; acc.y += e.y; acc.z += e.z; acc.w += e.w;
        }
        out4[o] = acc;
    }
}

__global__ void qsplit_k(const float* __restrict__ qk, const float* __restrict__ gamma,
                         const float* __restrict__ beta,
                         __nv_bfloat16* qqh, __nv_bfloat16* qql,
                         __nv_bfloat16* lqh, __nv_bfloat16* lql,
                         __nv_bfloat16* qkh, __nv_bfloat16* qkl,
                         float* lkf) {
    long i2 = (long)blockIdx.x * blockDim.x + threadIdx.x;      // over NT*DQK/2
    if (i2 >= (long)NT*DQK/2) return;
    int d = (int)((i2 & 63) * 2);
    float2 v = ((const float2*)qk)[i2];
    uint32_t hu, lu;
    float a0, a1;
    a0 = v.x * gamma[0*DQK + d] + beta[0*DQK + d];
    a1 = v.y * gamma[0*DQK + d+1] + beta[0*DQK + d+1];
    bsplit2(a0, a1, hu, lu);
    ((uint32_t*)qqh)[i2] = hu; ((uint32_t*)qql)[i2] = lu;
    a0 = v.x * gamma[1*DQK + d] + beta[1*DQK + d];
    a1 = v.y * gamma[1*DQK + d+1] + beta[1*DQK + d+1];
    bsplit2(a0, a1, hu, lu);
    ((uint32_t*)lqh)[i2] = hu; ((uint32_t*)lql)[i2] = lu;
    a0 = v.x * gamma[2*DQK + d] + beta[2*DQK + d];
    a1 = v.y * gamma[2*DQK + d+1] + beta[2*DQK + d+1];
    bsplit2(a0, a1, hu, lu);
    ((uint32_t*)qkh)[i2] = hu; ((uint32_t*)qkl)[i2] = lu;
    float2 lk;
    lk.x = v.x * gamma[3*DQK + d] + beta[3*DQK + d];
    lk.y = v.y * gamma[3*DQK + d+1] + beta[3*DQK + d+1];
    ((float2*)lkf)[i2] = lk;
}

__global__ void cumsum_split_k(const float* __restrict__ kvf,
                               __nv_bfloat16* __restrict__ oh,
                               __nv_bfloat16* __restrict__ ol) {
    const size_t S = (size_t)2048*128;
    long i2 = (long)blockIdx.x * blockDim.x + threadIdx.x;      // over Bb*S/2
    if (i2 >= (long)Bb*(S/2)) return;
    size_t b = (size_t)i2 / (S/2), r2 = (size_t)i2 % (S/2);
    size_t base2 = b*Gg*(S/2) + r2;
    float s0 = 0.f, s1 = 0.f;
    #pragma unroll
    for (int g = 0; g < Gg; g++) {
        size_t o2 = base2 + (size_t)g*(S/2);
        float2 v = ((const float2*)kvf)[o2];
        uint32_t hu, lu;
        bsplit2(s0, s1, hu, lu);
        ((uint32_t*)oh)[o2] = hu; ((uint32_t*)ol)[o2] = lu;
        s0 += v.x; s1 += v.y;
    }
}

// ================= HMMA bf16x2 GEMM — A split hi/lo, B hi only, 2-stage =========
// A stage row (144 B): cols 0-31 = A hi, cols 32-63 = A lo (K-chunk = 32).
// B stage row (80 B):  cols 0-31 = B hi.
// D = Ah*Bh + Al*Bh   (dropped a*bl term ~2^-9 relative; gate is 1e-3)
#define LDA 72            // A: bf16 elems per smem row = 144 B
#define LDB 40            // B: bf16 elems per smem row = 80 B
#define A_BYTES 18432     // 128 * 144
#define B_BYTES 10240     // 128 * 80
#define STG_BYTES (A_BYTES + B_BYTES)
#define GSMEM (2*STG_BYTES)

__global__ void __launch_bounds__(256, 2) gemm_k(
    const __nv_bfloat16* __restrict__ Ah, const __nv_bfloat16* __restrict__ Al,
    const __nv_bfloat16* __restrict__ Bh,
    float* C, __nv_bfloat16* Ch, __nv_bfloat16* Cl,
    int M, int N, int Ktot, const float* __restrict__ bias, float alpha, int flags,
    long long sA, long long sB, long long sC)
{
    extern __shared__ __align__(16) unsigned char smem[];
    uint32_t sbase = smem_to_u32(smem);
    int tid = threadIdx.x, lane = tid & 31, wid = tid >> 5;
    int wm = wid & 3, wn = wid >> 2;            // 4 (M) x 2 (N) warps
    int brow = blockIdx.y * 128, bcol = blockIdx.x * 128;
    long long bz = blockIdx.z;
    Ah += bz*sA; Al += bz*sA; Bh += bz*sB;
    if (C)  C  += bz*sC;
    if (Ch) { Ch += bz*sC; Cl += bz*sC; }

    // fully-masked score tile: zero-fill and exit
    if ((flags & F_SCORE) && bcol > brow) {
        uint4 z = make_uint4(0,0,0,0);
        for (int e = tid; e < 2048; e += 256) {
            int row = e >> 4, seg = e & 15;
            *(uint4*)(Ch + (size_t)(brow + row)*N + bcol + seg*8) = z;
            *(uint4*)(Cl + (size_t)(brow + row)*N + bcol + seg*8) = z;
        }
        return;
    }

    float acc[2][8][4];
    #pragma unroll
    for (int i = 0; i < 2; i++)
        #pragma unroll
        for (int j = 0; j < 8; j++)
            #pragma unroll
            for (int q = 0; q < 4; q++) acc[i][j][q] = 0.f;

    uint32_t aOff = (uint32_t)(((wm*32 + (lane & 15)) * LDA + (lane >> 4)*8) * 2);
    uint32_t bOff = (uint32_t)(((wn*64 + ((lane >> 4) & 1)*8 + (lane & 7)) * LDB
                                + ((lane >> 3) & 1)*8) * 2) + A_BYTES;
    const int ldr = tid >> 3, lds2 = tid & 7;   // A loader: 8 segs per 144B row
    const int segA = lds2 & 3;
    const int rb = tid >> 2, sb = tid & 3;      // B loader: 4 segs per 80B row

    int KC = Ktot >> 5;                         // 32-K chunks
    if (flags & F_TRIA) {                       // only K <= brow+128 contributes
        int kc2 = (brow + 128) >> 5;
        if (kc2 < KC) KC = kc2;
    }

    auto issue = [&](int it) {
        int k0 = it << 5;
        const __nv_bfloat16* As = (lds2 < 4) ? Ah : Al;
        uint32_t sa = sbase + (uint32_t)(it & 1)*STG_BYTES;
        #pragma unroll
        for (int e = 0; e < 4; e++) {
            int r = ldr + e*32;
            cp16(sa + (uint32_t)(r*144 + lds2*16),
                 As + (size_t)(brow + r)*Ktot + k0 + segA*8);
        }
        #pragma unroll
        for (int e = 0; e < 2; e++) {
            int r = rb + e*64;
            cp16(sa + (uint32_t)(A_BYTES + r*80 + sb*16),
                 Bh + (size_t)(bcol + r)*Ktot + k0 + sb*8);
        }
        CP_COMMIT();
    };

    issue(0);
    for (int it = 0; it < KC; ++it) {
        if (it + 1 < KC) { issue(it + 1); CP_WAIT(1); }
        else             { CP_WAIT(0); }
        __syncthreads();
        uint32_t stg = sbase + (uint32_t)(it & 1)*STG_BYTES;
        uint32_t aB = stg + aOff, bB = stg + bOff;
        #pragma unroll
        for (int kk = 0; kk < 2; kk++) {
            uint32_t afh[2][4], afl[2][4];
            #pragma unroll
            for (int i = 0; i < 2; i++) {
                ldsm4(afh[i], aB + (uint32_t)((i*16*LDA + kk*16) * 2));
                ldsm4(afl[i], aB + (uint32_t)((i*16*LDA + 32 + kk*16) * 2));
            }
            #pragma unroll
            for (int p = 0; p < 4; p++) {
                uint32_t bh[4];
                ldsm4(bh, bB + (uint32_t)((p*16*LDB + kk*16) * 2));
                #pragma unroll
                for (int i = 0; i < 2; i++) {
                    mma16816(acc[i][2*p],   afh[i], bh[0], bh[1]);
                    mma16816(acc[i][2*p+1], afh[i], bh[2], bh[3]);
                    mma16816(acc[i][2*p],   afl[i], bh[0], bh[1]);
                    mma16816(acc[i][2*p+1], afl[i], bh[2], bh[3]);
                }
            }
        }
        __syncthreads();
    }

    // ---- epilogue ----
    int g = lane >> 2, c2 = (lane & 3)*2;
    #pragma unroll
    for (int i = 0; i < 2; i++) {
        #pragma unroll
        for (int j = 0; j < 8; j++) {
            #pragma unroll
            for (int rr = 0; rr < 2; rr++) {
                int row = brow + wm*32 + i*16 + g + rr*8;
                int col = bcol + wn*64 + j*8 + c2;
                float v0 = acc[i][j][rr*2+0] * alpha;
                float v1 = acc[i][j][rr*2+1] * alpha;
                if (flags & F_SCORE) {
                    v0 = fmaxf(v0, 0.f); v0 *= v0;
                    v1 = fmaxf(v1, 0.f); v1 *= v1;
                    if (col     > row) v0 = 0.f;
                    if (col + 1 > row) v1 = 0.f;
                    size_t o = (size_t)row*N + col;
                    uint32_t hu, lu;
                    bsplit2(v0, v1, hu, lu);
                    *(uint32_t*)(Ch + o) = hu;
                    *(uint32_t*)(Cl + o) = lu;
                } else {
                    if (bias) { v0 += bias[col]; v1 += bias[col+1]; }
                    if (flags & F_SILU) {
                        v0 = v0 / (1.f + expf(-v0));
                        v1 = v1 / (1.f + expf(-v1));
                    }
                    size_t o = (size_t)row*N + col;
                    if (flags & F_ACC) { v0 += C[o]; v1 += C[o+1]; }
                    *(float2*)(C + o) = make_float2(v0, v1);
                }
            }
        }
    }
}

// ================= launcher =================
extern "C" void kernel_launch(void* const* d_in, const int* in_sizes, int n_in,
                              void* d_out, int out_size) {
    const float* x      = (const float*)d_in[0];
    const float* ln_h_g = (const float*)d_in[1];
    const float* ln_h_b = (const float*)d_in[2];
    const float* W_h    = (const float*)d_in[3];
    const float* b_h    = (const float*)d_in[4];
    const float* dw_h   = (const float*)d_in[5];
    const float* ln_qk_g= (const float*)d_in[6];
    const float* ln_qk_b= (const float*)d_in[7];
    const float* W_qk   = (const float*)d_in[8];
    const float* b_qk   = (const float*)d_in[9];
    const float* dw_qk  = (const float*)d_in[10];
    const float* gamma  = (const float*)d_in[11];
    const float* beta   = (const float*)d_in[12];
    const float* ln_o_g = (const float*)d_in[13];
    const float* ln_o_b = (const float*)d_in[14];
    const float* W_o    = (const float*)d_in[15];
    const float* b_o    = (const float*)d_in[16];
    const float* dw_o   = (const float*)d_in[17];
    float* out = (float*)d_out;

    unsigned char* pool;
    cudaGetSymbolAddress((void**)&pool, g_pool);
    float*         nx   = (float*)(pool + O_NX);
    __nv_bfloat16* lnH  = (__nv_bfloat16*)(pool + O_LNH);
    __nv_bfloat16* lnL  = (__nv_bfloat16*)(pool + O_LNL);
    __nv_bfloat16* whTH = (__nv_bfloat16*)(pool + O_WHTH);
    __nv_bfloat16* whTL = (__nv_bfloat16*)(pool + O_WHTL);
    __nv_bfloat16* wqTH = (__nv_bfloat16*)(pool + O_WQTH);
    __nv_bfloat16* wqTL = (__nv_bfloat16*)(pool + O_WQTL);
    __nv_bfloat16* woTH = (__nv_bfloat16*)(pool + O_WOTH);
    __nv_bfloat16* woTL = (__nv_bfloat16*)(pool + O_WOTL);
    float*         bufA = (float*)(pool + O_BUFA);
    float*         hid  = (float*)(pool + O_HID);
    __nv_bfloat16* hTH  = (__nv_bfloat16*)(pool + O_HTH);
    __nv_bfloat16* hTL  = (__nv_bfloat16*)(pool + O_HTL);
    float*         qk   = (float*)(pool + O_QK);
    float*         qk2  = (float*)(pool + O_QK2);
    __nv_bfloat16* qqH  = (__nv_bfloat16*)(pool + O_QQH);
    __nv_bfloat16* qqL  = (__nv_bfloat16*)(pool + O_QQL);
    __nv_bfloat16* lqH  = (__nv_bfloat16*)(pool + O_LQH);
    __nv_bfloat16* lqL  = (__nv_bfloat16*)(pool + O_LQL);
    __nv_bfloat16* qkH  = (__nv_bfloat16*)(pool + O_QKH);
    __nv_bfloat16* qkL  = (__nv_bfloat16*)(pool + O_QKL);
    float*         lkF  = (float*)(pool + O_LKF);
    __nv_bfloat16* lkTH = (__nv_bfloat16*)(pool + O_LKTH);
    __nv_bfloat16* lkTL = (__nv_bfloat16*)(pool + O_LKTL);
    __nv_bfloat16* attH = (__nv_bfloat16*)(pool + O_ATTH);
    __nv_bfloat16* attL = (__nv_bfloat16*)(pool + O_ATTL);
    float*         kvF  = (float*)(pool + O_KVF);
    __nv_bfloat16* kvH  = (__nv_bfloat16*)(pool + O_KVH);
    __nv_bfloat16* kvL  = (__nv_bfloat16*)(pool + O_KVL);
    float*         opre = nx;

    cudaFuncSetAttribute(gemm_k, cudaFuncAttributeMaxDynamicSharedMemorySize, GSMEM);

    // 1. token shift (float4)
    shift_k<<<(NT*(Dd/4) + 255)/256, 256>>>((const float4*)x, (float4*)nx);
    // 2. weight transposes -> bf16 hi/lo  [out,in] K-major (lo unused by 2-term GEMM)
    trans_split_k<<<dim3(2048/32, 512/32, 1), 256>>>(W_h,  whTH, whTL, 512, 2048);
    trans_split_k<<<dim3(128/32,  512/32, 1), 256>>>(W_qk, wqTH, wqTL, 512, 128);
    trans_split_k<<<dim3(512/32, 1024/32, 1), 256>>>(W_o,  woTH, woTL, 1024, 512);
    // 3. LN_h -> hi/lo
    ln_split_k<<<NT, 256>>>(nx, ln_h_g, ln_h_b, lnH, lnL, Dd);
    // 4. GEMM1 -> bufA (SiLU)
    gemm_k<<<dim3(16, 128, 1), 256, GSMEM>>>(lnH, lnL, whTH, bufA, nullptr, nullptr,
        NT, HIDc, Dd, b_h, 1.f, F_SILU, 0, 0, 0);
    // 5. dwconv -> hid
    dwconv4_k<<<dim3(32, 16, Bb), 256>>>((const float4*)bufA, dw_h, nullptr,
                                         (float4*)hid, HIDc);
    // 6. hid per-group transpose -> hT [bg,2048,256]
    trans_split_k<<<dim3(64, 8, 64), 256>>>(hid, hTH, hTL, 256, 2048);
    // 7. LN_qk -> hi/lo
    ln_split_k<<<NT, 256>>>(nx, ln_qk_g, ln_qk_b, lnH, lnL, Dd);
    // 8. GEMM2 -> qk (SiLU)
    gemm_k<<<dim3(1, 128, 1), 256, GSMEM>>>(lnH, lnL, wqTH, qk, nullptr, nullptr,
        NT, DQK, Dd, b_qk, 1.f, F_SILU, 0, 0, 0);
    // 9. dwconv -> qk2
    dwconv4_k<<<dim3(2, 16, Bb), 256>>>((const float4*)qk, dw_qk, nullptr,
                                        (float4*)qk2, DQK);
    // 10. offset-scale split
    qsplit_k<<<(NT*DQK/2 + 255)/256, 256>>>(qk2, gamma, beta, qqH, qqL, lqH, lqL, qkH, qkL, lkF);
    // 11. lin_k per-group transpose -> lkT [bg,128,256]
    trans_split_k<<<dim3(4, 8, 64), 256>>>(lkF, lkTH, lkTL, 256, 128);
    // 12. scores -> attH/attL (relu^2 causal, bf16 split); B = quad_k hi
    gemm_k<<<dim3(2, 2, 64), 256, GSMEM>>>(qqH, qqL, qkH, nullptr, attH, attL,
        GRP, GRP, DQK, nullptr, 1.f/GRP, F_SCORE,
        (long long)GRP*DQK, (long long)GRP*DQK, (long long)GRP*GRP);
    // 13. quad out: attn @ hidT^T -> bufA (triangular K-skip); B = hT hi
    gemm_k<<<dim3(16, 2, 64), 256, GSMEM>>>(attH, attL, hTH, bufA, nullptr, nullptr,
        GRP, HIDc, GRP, nullptr, 1.f, F_TRIA,
        (long long)GRP*GRP, (long long)HIDc*GRP, (long long)GRP*HIDc);
    // 14. lin kv (coalesced): out[e,d] = sum_n hT[e,n]*lkT[d,n] / g; A = hT (split), B = lkT hi
    gemm_k<<<dim3(1, 16, 64), 256, GSMEM>>>(hTH, hTL, lkTH, kvF, nullptr, nullptr,
        HIDc, DQK, GRP, nullptr, 1.f/GRP, 0,
        (long long)HIDc*GRP, (long long)DQK*GRP, (long long)HIDc*DQK);
    // 15. exclusive group cumsum -> kvH/kvL
    cumsum_split_k<<<(int)(((size_t)Bb*2048*64 + 255)/256), 256>>>(kvF, kvH, kvL);
    // 16. lin out: lin_q (split) @ kvT hi, accumulate into bufA
    gemm_k<<<dim3(16, 2, 64), 256, GSMEM>>>(lqH, lqL, kvH, bufA, nullptr, nullptr,
        GRP, HIDc, DQK, nullptr, 1.f, F_ACC,
        (long long)GRP*DQK, (long long)HIDc*DQK, (long long)GRP*HIDc);
    // 17. fused gating + LN_o -> lnH/lnL
    gate_ln_k<<<NT, 256>>>(bufA, hid, ln_o_g, ln_o_b, lnH, lnL);
    // 18. GEMM3 -> opre (SiLU)
    gemm_k<<<dim3(4, 128, 1), 256, GSMEM>>>(lnH, lnL, woTH, opre, nullptr, nullptr,
        NT, Dd, 2*Dd, b_o, 1.f, F_SILU, 0, 0, 0);
    // 19. dwconv + x residual -> out
    dwconv4_k<<<dim3(8, 16, Bb), 256>>>((const float4*)opre, dw_o, (const float4*)x,
                                        (float4*)out, Dd);
}

// round 10
// speedup vs baseline: 1.6348x; 1.3787x over previous
#include <cuda_runtime.h>
#include <cuda_bf16.h>
#include <cstdint>

#define Bb    8
#define Nn    2048
#define Dd    512
#define HIDc  2048
#define DQK   128
#define GRP   256
#define Gg    8
#define NT    (Bb*Nn)
#define Ee    1024
#define KK    17

// ================= warp MMA / async helpers (sm_80+ portable) =================
__device__ __forceinline__ uint32_t smem_to_u32(const void* p) {
    uint32_t a;
    asm("{ .reg .u64 t; cvta.to.shared.u64 t, %1; cvt.u32.u64 %0, t; }" : "=r"(a) : "l"(p));
    return a;
}
__device__ __forceinline__ void ldsm4(uint32_t* r, uint32_t addr) {
    asm volatile("ldmatrix.sync.aligned.m8n8.x4.shared.b16 {%0,%1,%2,%3}, [%4];"
        : "=r"(r[0]), "=r"(r[1]), "=r"(r[2]), "=r"(r[3]) : "r"(addr));
}
__device__ __forceinline__ void mma16816(float* c, const uint32_t* a, uint32_t b0, uint32_t b1) {
    asm volatile(
        "mma.sync.aligned.m16n8k16.row.col.f32.bf16.bf16.f32 "
        "{%0,%1,%2,%3}, {%4,%5,%6,%7}, {%8,%9}, {%0,%1,%2,%3};"
        : "+f"(c[0]), "+f"(c[1]), "+f"(c[2]), "+f"(c[3])
        : "r"(a[0]), "r"(a[1]), "r"(a[2]), "r"(a[3]), "r"(b0), "r"(b1));
}
__device__ __forceinline__ void cp16(uint32_t dst, const void* src) {
    asm volatile("cp.async.cg.shared.global [%0], [%1], 16;" :: "r"(dst), "l"(src));
}
#define CP_COMMIT() asm volatile("cp.async.commit_group;" ::: "memory")
#define CP_WAIT(N)  asm volatile("cp.async.wait_group %0;" :: "n"(N) : "memory")

#define F_SILU  1
#define F_ACC   2
#define F_SCORE 4
#define F_TRIA  16   // A block-lower-triangular in K: only K <= brow+128 contributes

// ================= scratch pool =================
#define SZF(n) ((size_t)(n)*4)
#define SZB(n) ((size_t)(n)*2)
static constexpr size_t O_NX   = 0;
static constexpr size_t O_LNH  = O_NX   + SZF((size_t)NT*512);      // bf16 [NT,1024]
static constexpr size_t O_WHTH = O_LNH  + SZB((size_t)NT*1024);     // bf16 [2048,512]
static constexpr size_t O_WQTH = O_WHTH + SZB(2048*512);            // bf16 [128,512]
static constexpr size_t O_WOTH = O_WQTH + SZB(128*512);             // bf16 [512,1024]
static constexpr size_t O_BUFA = O_WOTH + SZB(512*1024);            // f32 [NT,2048]
static constexpr size_t O_HID  = O_BUFA + SZF((size_t)NT*2048);     // f32 [NT,2048]
static constexpr size_t O_HTH  = O_HID  + SZF((size_t)NT*2048);     // bf16 [bg,2048,256]
static constexpr size_t O_QK   = O_HTH  + SZB((size_t)NT*2048);     // f32 [NT,128]
static constexpr size_t O_QK2  = O_QK   + SZF((size_t)NT*128);
static constexpr size_t O_QQH  = O_QK2  + SZF((size_t)NT*128);      // bf16 [NT,128] x3
static constexpr size_t O_LQH  = O_QQH  + SZB((size_t)NT*128);
static constexpr size_t O_QKH  = O_LQH  + SZB((size_t)NT*128);
static constexpr size_t O_LKF  = O_QKH  + SZB((size_t)NT*128);      // f32 [NT,128]
static constexpr size_t O_LKTH = O_LKF  + SZF((size_t)NT*128);      // bf16 [bg,128,256]
static constexpr size_t O_ATTH = O_LKTH + SZB((size_t)NT*128);      // bf16 [bg,256,256]
static constexpr size_t O_KVF  = O_ATTH + SZB((size_t)64*256*256);  // f32 [bg,2048,128]
static constexpr size_t O_KVH  = O_KVF  + SZF((size_t)64*2048*128); // bf16 [bg,2048,128]
static constexpr size_t O_END  = O_KVH  + SZB((size_t)64*2048*128);
__device__ __align__(1024) unsigned char g_pool[O_END];

__device__ __forceinline__ uint32_t pack_bf2(float v0, float v1) {
    __nv_bfloat16 h0 = __float2bfloat16(v0), h1 = __float2bfloat16(v1);
    return ((uint32_t)__bfloat16_as_ushort(h1) << 16) | __bfloat16_as_ushort(h0);
}

// ================= elementwise / prep kernels =================
__global__ void shift_k(const float4* __restrict__ x, float4* __restrict__ nx) {
    long i = (long)blockIdx.x * blockDim.x + threadIdx.x;
    if (i >= (long)NT*(Dd/4)) return;
    int c4 = (int)(i % (Dd/4));
    int n  = (int)((i / (Dd/4)) % Nn);
    if (c4 < Dd/8) nx[i] = (n == 0) ? make_float4(0,0,0,0) : x[i - Dd/4];
    else           nx[i] = x[i];
}

__global__ void ln_bf16_k(const float* __restrict__ in, const float* __restrict__ g,
                          const float* __restrict__ b,
                          __nv_bfloat16* __restrict__ oh, int C) {
    long row = blockIdx.x;
    const float2* xr2 = (const float2*)(in + row * C);
    int C2 = C >> 1;
    float s = 0.f, s2 = 0.f;
    for (int i = threadIdx.x; i < C2; i += blockDim.x) {
        float2 v = xr2[i]; s += v.x + v.y; s2 += v.x*v.x + v.y*v.y;
    }
    #pragma unroll
    for (int o = 16; o; o >>= 1) {
        s  += __shfl_xor_sync(~0u, s,  o);
        s2 += __shfl_xor_sync(~0u, s2, o);
    }
    __shared__ float shs[8], shs2[8], smu, sinv;
    int w = threadIdx.x >> 5, l = threadIdx.x & 31;
    if (l == 0) { shs[w] = s; shs2[w] = s2; }
    __syncthreads();
    if (threadIdx.x == 0) {
        float ts = 0.f, ts2 = 0.f;
        for (int i = 0; i < (int)(blockDim.x >> 5); i++) { ts += shs[i]; ts2 += shs2[i]; }
        float mu = ts / C;
        smu = mu; sinv = rsqrtf(ts2 / C - mu*mu + 1e-5f);
    }
    __syncthreads();
    float mu = smu, inv = sinv;
    uint32_t* oh2 = (uint32_t*)(oh + row*C);
    const float2* g2 = (const float2*)g;
    const float2* b2 = (const float2*)b;
    for (int i = threadIdx.x; i < C2; i += blockDim.x) {
        float2 xv = xr2[i], gv = g2[i], bv = b2[i];
        float v0 = (xv.x - mu) * inv * gv.x + bv.x;
        float v1 = (xv.y - mu) * inv * gv.y + bv.y;
        oh2[i] = pack_bf2(v0, v1);
    }
}

// fused gating + LN(1024) -> bf16
__global__ void gate_ln_k(const float* __restrict__ att, const float* __restrict__ hid,
                          const float* __restrict__ g, const float* __restrict__ b,
                          __nv_bfloat16* __restrict__ oh) {
    long row = blockIdx.x;
    __shared__ float buf[1024];
    const float2* ar  = (const float2*)(att + row*HIDc);
    const float2* ar2 = (const float2*)(att + row*HIDc + Ee);
    const float2* hr  = (const float2*)(hid + row*HIDc);
    const float2* hr2 = (const float2*)(hid + row*HIDc + Ee);
    float s = 0.f, s2 = 0.f;
    for (int i = threadIdx.x; i < 512; i += blockDim.x) {
        float2 av = ar[i], au = ar2[i], v = hr[i], u = hr2[i];
        float t0 = au.x * v.x * (1.f / (1.f + expf(-(av.x * u.x))));
        float t1 = au.y * v.y * (1.f / (1.f + expf(-(av.y * u.y))));
        buf[2*i] = t0; buf[2*i+1] = t1;
        s += t0 + t1; s2 += t0*t0 + t1*t1;
    }
    #pragma unroll
    for (int o = 16; o; o >>= 1) {
        s  += __shfl_xor_sync(~0u, s,  o);
        s2 += __shfl_xor_sync(~0u, s2, o);
    }
    __shared__ float shs[8], shs2[8], smu, sinv;
    int w = threadIdx.x >> 5, l = threadIdx.x & 31;
    if (l == 0) { shs[w] = s; shs2[w] = s2; }
    __syncthreads();
    if (threadIdx.x == 0) {
        float ts = 0.f, ts2 = 0.f;
        for (int i = 0; i < (int)(blockDim.x >> 5); i++) { ts += shs[i]; ts2 += shs2[i]; }
        float mu = ts / 1024.f;
        smu = mu; sinv = rsqrtf(ts2 / 1024.f - mu*mu + 1e-5f);
    }
    __syncthreads();
    float mu = smu, inv = sinv;
    uint32_t* oh2 = (uint32_t*)(oh + row*1024);
    for (int i = threadIdx.x; i < 512; i += blockDim.x) {
        float v0 = (buf[2*i]   - mu) * inv * g[2*i]   + b[2*i];
        float v1 = (buf[2*i+1] - mu) * inv * g[2*i+1] + b[2*i+1];
        oh2[i] = pack_bf2(v0, v1);
    }
}

// vectorized transpose fp32 [R,C] -> bf16 [C,R], batched via blockIdx.z
__global__ void trans_bf16_k(const float* __restrict__ in,
                             __nv_bfloat16* __restrict__ oh, int R, int C) {
    __shared__ float s[32][36];
    size_t bz = (size_t)blockIdx.z * R * C;
    int c0 = blockIdx.x * 32, r0 = blockIdx.y * 32;
    int t = threadIdx.x;
    {
        int r = t >> 3, c4 = (t & 7) * 4;
        *(float4*)&s[r][c4] = *(const float4*)(in + bz + (size_t)(r0 + r)*C + c0 + c4);
    }
    __syncthreads();
    {
        int c = t & 31, rg = (t >> 5) * 4;
        uint32_t h01 = pack_bf2(s[rg][c],   s[rg+1][c]);
        uint32_t h23 = pack_bf2(s[rg+2][c], s[rg+3][c]);
        size_t o = bz + (size_t)(c0 + c)*R + r0 + rg;
        *(uint2*)(oh + o) = make_uint2(h01, h23);
    }
}

// float4-vectorized depthwise conv K=17 + residual (+ optional extra residual)
__global__ void dwconv4_k(const float4* __restrict__ h4, const float* __restrict__ dw,
                          const float4* __restrict__ extra4, float4* __restrict__ out4, int C) {
    const int CT4 = 16, NTile = 128, HALO = 8;
    __shared__ float4 sh[NTile + 2*HALO][CT4];
    __shared__ float4 sdw[KK][CT4];
    int b = blockIdx.z, n0 = blockIdx.y * NTile, c0 = blockIdx.x * CT4;
    int C4 = C >> 2;
    const float4* base = h4 + (size_t)b*Nn*C4 + c0;
    for (int idx = threadIdx.x; idx < (NTile + 2*HALO)*CT4; idx += blockDim.x) {
        int r = idx >> 4, c = idx & 15;
        int n = n0 - HALO + r;
        sh[r][c] = (n >= 0 && n < Nn) ? base[(size_t)n*C4 + c] : make_float4(0,0,0,0);
    }
    for (int idx = threadIdx.x; idx < KK*CT4; idx += blockDim.x) {
        int k = idx >> 4, c = idx & 15;
        const float* w = dw + k*C + (c0 + c)*4;
        sdw[k][c] = make_float4(w[0], w[1], w[2], w[3]);
    }
    __syncthreads();
    for (int idx = threadIdx.x; idx < NTile*CT4; idx += blockDim.x) {
        int r = idx >> 4, c = idx & 15;
        float4 acc = sh[r + HALO][c];
        #pragma unroll
        for (int k = 0; k < KK; k++) {
            float4 a = sh[r + k][c], w = sdw[k][c];
            acc.x += a.x*w.x; acc.y += a.y*w.y; acc.z += a.z*w.z; acc.w += a.w*w.w;
        }
        size_t o = (size_t)b*Nn*C4 + (size_t)(n0 + r)*C4 + c0 + c;
        if (extra4) {
            float4 e = extra4[o];
            acc.x += e.x; acc.y += e.y; acc.z += e.z; acc.w += e.w;
        }
        out4[o] = acc;
    }
}

__global__ void qsplit_k(const float* __restrict__ qk, const float* __restrict__ gamma,
                         const float* __restrict__ beta,
                         __nv_bfloat16* qqh, __nv_bfloat16* lqh, __nv_bfloat16* qkh,
                         float* lkf) {
    long i2 = (long)blockIdx.x * blockDim.x + threadIdx.x;      // over NT*DQK/2
    if (i2 >= (long)NT*DQK/2) return;
    int d = (int)((i2 & 63) * 2);
    float2 v = ((const float2*)qk)[i2];
    ((uint32_t*)qqh)[i2] = pack_bf2(v.x * gamma[0*DQK + d]   + beta[0*DQK + d],
                                    v.y * gamma[0*DQK + d+1] + beta[0*DQK + d+1]);
    ((uint32_t*)lqh)[i2] = pack_bf2(v.x * gamma[1*DQK + d]   + beta[1*DQK + d],
                                    v.y * gamma[1*DQK + d+1] + beta[1*DQK + d+1]);
    ((uint32_t*)qkh)[i2] = pack_bf2(v.x * gamma[2*DQK + d]   + beta[2*DQK + d],
                                    v.y * gamma[2*DQK + d+1] + beta[2*DQK + d+1]);
    float2 lk;
    lk.x = v.x * gamma[3*DQK + d] + beta[3*DQK + d];
    lk.y = v.y * gamma[3*DQK + d+1] + beta[3*DQK + d+1];
    ((float2*)lkf)[i2] = lk;
}

__global__ void cumsum_bf16_k(const float* __restrict__ kvf,
                              __nv_bfloat16* __restrict__ oh) {
    const size_t S = (size_t)2048*128;
    long i2 = (long)blockIdx.x * blockDim.x + threadIdx.x;      // over Bb*S/2
    if (i2 >= (long)Bb*(S/2)) return;
    size_t b = (size_t)i2 / (S/2), r2 = (size_t)i2 % (S/2);
    size_t base2 = b*Gg*(S/2) + r2;
    float s0 = 0.f, s1 = 0.f;
    #pragma unroll
    for (int g = 0; g < Gg; g++) {
        size_t o2 = base2 + (size_t)g*(S/2);
        float2 v = ((const float2*)kvf)[o2];
        ((uint32_t*)oh)[o2] = pack_bf2(s0, s1);
        s0 += v.x; s1 += v.y;
    }
}

// ================= HMMA bf16 GEMM — single-term, 128x128 tile, 2-stage =========
// D[m,n] = sum_k A[m,k]*B[n,k], K-major bf16, K-chunk = 64 per stage.
#define LDA 72            // bf16 elems per smem row (64 data + 8 pad) = 144 B
#define STG_BYTES 36864   // one stage: A (18432) + B (18432)
#define GSMEM (2*STG_BYTES)

__global__ void __launch_bounds__(256, 2) gemm_k(
    const __nv_bfloat16* __restrict__ Ah, const __nv_bfloat16* __restrict__ Bh,
    float* C, __nv_bfloat16* Ch,
    int M, int N, int Ktot, const float* __restrict__ bias, float alpha, int flags,
    long long sA, long long sB, long long sC)
{
    extern __shared__ __align__(16) unsigned char smem[];
    uint32_t sbase = smem_to_u32(smem);
    int tid = threadIdx.x, lane = tid & 31, wid = tid >> 5;
    int wm = wid & 3, wn = wid >> 2;            // 4 (M) x 2 (N) warps
    int brow = blockIdx.y * 128, bcol = blockIdx.x * 128;
    long long bz = blockIdx.z;
    Ah += bz*sA; Bh += bz*sB;
    if (C)  C  += bz*sC;
    if (Ch) Ch += bz*sC;

    // fully-masked score tile: zero-fill and exit
    if ((flags & F_SCORE) && bcol > brow) {
        uint4 z = make_uint4(0,0,0,0);
        for (int e = tid; e < 2048; e += 256) {
            int row = e >> 4, seg = e & 15;
            *(uint4*)(Ch + (size_t)(brow + row)*N + bcol + seg*8) = z;
        }
        return;
    }

    float acc[2][8][4];
    #pragma unroll
    for (int i = 0; i < 2; i++)
        #pragma unroll
        for (int j = 0; j < 8; j++)
            #pragma unroll
            for (int q = 0; q < 4; q++) acc[i][j][q] = 0.f;

    uint32_t aOff = (uint32_t)(((wm*32 + (lane & 15)) * LDA + (lane >> 4)*8) * 2);
    uint32_t bOff = (uint32_t)(((wn*64 + ((lane >> 4) & 1)*8 + (lane & 7)) * LDA
                                + ((lane >> 3) & 1)*8) * 2) + 18432;
    const int ldr = tid >> 3, lds2 = tid & 7;   // 8 x 16B segments per 144B row

    int KC = Ktot >> 6;                         // 64-K chunks
    if (flags & F_TRIA) {                       // only K <= brow+128 contributes
        int kc2 = (brow + 128) >> 6;
        if (kc2 < KC) KC = kc2;
    }

    auto issue = [&](int it) {
        int k0 = it << 6;
        uint32_t sa = sbase + (uint32_t)(it & 1)*STG_BYTES;
        #pragma unroll
        for (int e = 0; e < 4; e++) {
            int r = ldr + e*32;
            cp16(sa + (uint32_t)(r*144 + lds2*16),
                 Ah + (size_t)(brow + r)*Ktot + k0 + lds2*8);
            cp16(sa + 18432u + (uint32_t)(r*144 + lds2*16),
                 Bh + (size_t)(bcol + r)*Ktot + k0 + lds2*8);
        }
        CP_COMMIT();
    };

    issue(0);
    for (int it = 0; it < KC; ++it) {
        if (it + 1 < KC) { issue(it + 1); CP_WAIT(1); }
        else             { CP_WAIT(0); }
        __syncthreads();
        uint32_t stg = sbase + (uint32_t)(it & 1)*STG_BYTES;
        uint32_t aB = stg + aOff, bB = stg + bOff;
        #pragma unroll
        for (int kk = 0; kk < 4; kk++) {
            uint32_t af[2][4], bfr[4][4];
            #pragma unroll
            for (int i = 0; i < 2; i++)
                ldsm4(af[i], aB + (uint32_t)((i*16*LDA + kk*16) * 2));
            #pragma unroll
            for (int p = 0; p < 4; p++)
                ldsm4(bfr[p], bB + (uint32_t)((p*16*LDA + kk*16) * 2));
            #pragma unroll
            for (int i = 0; i < 2; i++)
                #pragma unroll
                for (int j = 0; j < 8; j++)
                    mma16816(acc[i][j], af[i], bfr[j>>1][(j&1)*2], bfr[j>>1][(j&1)*2+1]);
        }
        __syncthreads();
    }

    // ---- epilogue ----
    int g = lane >> 2, c2 = (lane & 3)*2;
    #pragma unroll
    for (int i = 0; i < 2; i++) {
        #pragma unroll
        for (int j = 0; j < 8; j++) {
            #pragma unroll
            for (int rr = 0; rr < 2; rr++) {
                int row = brow + wm*32 + i*16 + g + rr*8;
                int col = bcol + wn*64 + j*8 + c2;
                float v0 = acc[i][j][rr*2+0] * alpha;
                float v1 = acc[i][j][rr*2+1] * alpha;
                if (flags & F_SCORE) {
                    v0 = fmaxf(v0, 0.f); v0 *= v0;
                    v1 = fmaxf(v1, 0.f); v1 *= v1;
                    if (col     > row) v0 = 0.f;
                    if (col + 1 > row) v1 = 0.f;
                    *(uint32_t*)(Ch + (size_t)row*N + col) = pack_bf2(v0, v1);
                } else {
                    if (bias) { v0 += bias[col]; v1 += bias[col+1]; }
                    if (flags & F_SILU) {
                        v0 = v0 / (1.f + expf(-v0));
                        v1 = v1 / (1.f + expf(-v1));
                    }
                    size_t o = (size_t)row*N + col;
                    if (flags & F_ACC) { v0 += C[o]; v1 += C[o+1]; }
                    *(float2*)(C + o) = make_float2(v0, v1);
                }
            }
        }
    }
}

// ================= launcher =================
extern "C" void kernel_launch(void* const* d_in, const int* in_sizes, int n_in,
                              void* d_out, int out_size) {
    const float* x      = (const float*)d_in[0];
    const float* ln_h_g = (const float*)d_in[1];
    const float* ln_h_b = (const float*)d_in[2];
    const float* W_h    = (const float*)d_in[3];
    const float* b_h    = (const float*)d_in[4];
    const float* dw_h   = (const float*)d_in[5];
    const float* ln_qk_g= (const float*)d_in[6];
    const float* ln_qk_b= (const float*)d_in[7];
    const float* W_qk   = (const float*)d_in[8];
    const float* b_qk   = (const float*)d_in[9];
    const float* dw_qk  = (const float*)d_in[10];
    const float* gamma  = (const float*)d_in[11];
    const float* beta   = (const float*)d_in[12];
    const float* ln_o_g = (const float*)d_in[13];
    const float* ln_o_b = (const float*)d_in[14];
    const float* W_o    = (const float*)d_in[15];
    const float* b_o    = (const float*)d_in[16];
    const float* dw_o   = (const float*)d_in[17];
    float* out = (float*)d_out;

    unsigned char* pool;
    cudaGetSymbolAddress((void**)&pool, g_pool);
    float*         nx   = (float*)(pool + O_NX);
    __nv_bfloat16* lnH  = (__nv_bfloat16*)(pool + O_LNH);
    __nv_bfloat16* whTH = (__nv_bfloat16*)(pool + O_WHTH);
    __nv_bfloat16* wqTH = (__nv_bfloat16*)(pool + O_WQTH);
    __nv_bfloat16* woTH = (__nv_bfloat16*)(pool + O_WOTH);
    float*         bufA = (float*)(pool + O_BUFA);
    float*         hid  = (float*)(pool + O_HID);
    __nv_bfloat16* hTH  = (__nv_bfloat16*)(pool + O_HTH);
    float*         qk   = (float*)(pool + O_QK);
    float*         qk2  = (float*)(pool + O_QK2);
    __nv_bfloat16* qqH  = (__nv_bfloat16*)(pool + O_QQH);
    __nv_bfloat16* lqH  = (__nv_bfloat16*)(pool + O_LQH);
    __nv_bfloat16* qkH  = (__nv_bfloat16*)(pool + O_QKH);
    float*         lkF  = (float*)(pool + O_LKF);
    __nv_bfloat16* lkTH = (__nv_bfloat16*)(pool + O_LKTH);
    __nv_bfloat16* attH = (__nv_bfloat16*)(pool + O_ATTH);
    float*         kvF  = (float*)(pool + O_KVF);
    __nv_bfloat16* kvH  = (__nv_bfloat16*)(pool + O_KVH);
    float*         opre = nx;

    cudaFuncSetAttribute(gemm_k, cudaFuncAttributeMaxDynamicSharedMemorySize, GSMEM);

    // 1. token shift (float4)
    shift_k<<<(NT*(Dd/4) + 255)/256, 256>>>((const float4*)x, (float4*)nx);
    // 2. weight transposes -> bf16 [out,in] K-major
    trans_bf16_k<<<dim3(2048/32, 512/32, 1), 256>>>(W_h,  whTH, 512, 2048);
    trans_bf16_k<<<dim3(128/32,  512/32, 1), 256>>>(W_qk, wqTH, 512, 128);
    trans_bf16_k<<<dim3(512/32, 1024/32, 1), 256>>>(W_o,  woTH, 1024, 512);
    // 3. LN_h -> bf16
    ln_bf16_k<<<NT, 256>>>(nx, ln_h_g, ln_h_b, lnH, Dd);
    // 4. GEMM1 -> bufA (SiLU)
    gemm_k<<<dim3(16, 128, 1), 256, GSMEM>>>(lnH, whTH, bufA, nullptr,
        NT, HIDc, Dd, b_h, 1.f, F_SILU, 0, 0, 0);
    // 5. dwconv -> hid
    dwconv4_k<<<dim3(32, 16, Bb), 256>>>((const float4*)bufA, dw_h, nullptr,
                                         (float4*)hid, HIDc);
    // 6. hid per-group transpose -> hT [bg,2048,256]
    trans_bf16_k<<<dim3(64, 8, 64), 256>>>(hid, hTH, 256, 2048);
    // 7. LN_qk -> bf16
    ln_bf16_k<<<NT, 256>>>(nx, ln_qk_g, ln_qk_b, lnH, Dd);
    // 8. GEMM2 -> qk (SiLU)
    gemm_k<<<dim3(1, 128, 1), 256, GSMEM>>>(lnH, wqTH, qk, nullptr,
        NT, DQK, Dd, b_qk, 1.f, F_SILU, 0, 0, 0);
    // 9. dwconv -> qk2
    dwconv4_k<<<dim3(2, 16, Bb), 256>>>((const float4*)qk, dw_qk, nullptr,
                                        (float4*)qk2, DQK);
    // 10. offset-scale split
    qsplit_k<<<(NT*DQK/2 + 255)/256, 256>>>(qk2, gamma, beta, qqH, lqH, qkH, lkF);
    // 11. lin_k per-group transpose -> lkT [bg,128,256]
    trans_bf16_k<<<dim3(4, 8, 64), 256>>>(lkF, lkTH, 256, 128);
    // 12. scores -> attH (relu^2 causal, bf16)
    gemm_k<<<dim3(2, 2, 64), 256, GSMEM>>>(qqH, qkH, nullptr, attH,
        GRP, GRP, DQK, nullptr, 1.f/GRP, F_SCORE,
        (long long)GRP*DQK, (long long)GRP*DQK, (long long)GRP*GRP);
    // 13. quad out: attn @ hidT^T -> bufA (triangular K-skip)
    gemm_k<<<dim3(16, 2, 64), 256, GSMEM>>>(attH, hTH, bufA, nullptr,
        GRP, HIDc, GRP, nullptr, 1.f, F_TRIA,
        (long long)GRP*GRP, (long long)HIDc*GRP, (long long)GRP*HIDc);
    // 14. lin kv (coalesced): out[e,d] = sum_n hT[e,n]*lkT[d,n] / g
    gemm_k<<<dim3(1, 16, 64), 256, GSMEM>>>(hTH, lkTH, kvF, nullptr,
        HIDc, DQK, GRP, nullptr, 1.f/GRP, 0,
        (long long)HIDc*GRP, (long long)DQK*GRP, (long long)HIDc*DQK);
    // 15. exclusive group cumsum -> kvH
    cumsum_bf16_k<<<(int)(((size_t)Bb*2048*64 + 255)/256), 256>>>(kvF, kvH);
    // 16. lin out: lin_q @ kvT hi, accumulate into bufA
    gemm_k<<<dim3(16, 2, 64), 256, GSMEM>>>(lqH, kvH, bufA, nullptr,
        GRP, HIDc, DQK, nullptr, 1.f, F_ACC,
        (long long)GRP*DQK, (long long)HIDc*DQK, (long long)GRP*HIDc);
    // 17. fused gating + LN_o -> lnH
    gate_ln_k<<<NT, 256>>>(bufA, hid, ln_o_g, ln_o_b, lnH);
    // 18. GEMM3 -> opre (SiLU)
    gemm_k<<<dim3(4, 128, 1), 256, GSMEM>>>(lnH, woTH, opre, nullptr,
        NT, Dd, 2*Dd, b_o, 1.f, F_SILU, 0, 0, 0);
    // 19. dwconv + x residual -> out
    dwconv4_k<<<dim3(8, 16, Bb), 256>>>((const float4*)opre, dw_o, (const float4*)x,
                                        (float4*)out, Dd);
}

// round 11
// speedup vs baseline: 1.8210x; 1.1139x over previous
#include <cuda_runtime.h>
#include <cuda_bf16.h>
#include <cstdint>

#define Bb    8
#define Nn    2048
#define Dd    512
#define HIDc  2048
#define DQK   128
#define GRP   256
#define Gg    8
#define NT    (Bb*Nn)
#define Ee    1024
#define KK    17

// ================= warp MMA / async helpers (sm_80+ portable) =================
__device__ __forceinline__ uint32_t smem_to_u32(const void* p) {
    uint32_t a;
    asm("{ .reg .u64 t; cvta.to.shared.u64 t, %1; cvt.u32.u64 %0, t; }" : "=r"(a) : "l"(p));
    return a;
}
__device__ __forceinline__ void ldsm4(uint32_t* r, uint32_t addr) {
    asm volatile("ldmatrix.sync.aligned.m8n8.x4.shared.b16 {%0,%1,%2,%3}, [%4];"
        : "=r"(r[0]), "=r"(r[1]), "=r"(r[2]), "=r"(r[3]) : "r"(addr));
}
__device__ __forceinline__ void mma16816(float* c, const uint32_t* a, uint32_t b0, uint32_t b1) {
    asm volatile(
        "mma.sync.aligned.m16n8k16.row.col.f32.bf16.bf16.f32 "
        "{%0,%1,%2,%3}, {%4,%5,%6,%7}, {%8,%9}, {%0,%1,%2,%3};"
        : "+f"(c[0]), "+f"(c[1]), "+f"(c[2]), "+f"(c[3])
        : "r"(a[0]), "r"(a[1]), "r"(a[2]), "r"(a[3]), "r"(b0), "r"(b1));
}
__device__ __forceinline__ void cp16(uint32_t dst, const void* src) {
    asm volatile("cp.async.cg.shared.global [%0], [%1], 16;" :: "r"(dst), "l"(src));
}
#define CP_COMMIT() asm volatile("cp.async.commit_group;" ::: "memory")
#define CP_WAIT(N)  asm volatile("cp.async.wait_group %0;" :: "n"(N) : "memory")

#define F_SILU  1
#define F_SCORE 4
#define F_TRIA  16   // part-1 A block-lower-triangular in K: only K <= brow+128 contributes

// ================= scratch pool =================
#define SZF(n) ((size_t)(n)*4)
#define SZB(n) ((size_t)(n)*2)
static constexpr size_t O_NX   = 0;
static constexpr size_t O_LNH  = O_NX   + SZF((size_t)NT*512);      // bf16 [NT,1024]
static constexpr size_t O_WHTH = O_LNH  + SZB((size_t)NT*1024);     // bf16 [2048,512]
static constexpr size_t O_WQTH = O_WHTH + SZB(2048*512);            // bf16 [128,512]
static constexpr size_t O_WOTH = O_WQTH + SZB(128*512);             // bf16 [512,1024]
static constexpr size_t O_BUFA = O_WOTH + SZB(512*1024);            // f32 [NT,2048]
static constexpr size_t O_HID  = O_BUFA + SZF((size_t)NT*2048);     // f32 [NT,2048]
static constexpr size_t O_HTH  = O_HID  + SZF((size_t)NT*2048);     // bf16 [bg,2048,256]
static constexpr size_t O_QK   = O_HTH  + SZB((size_t)NT*2048);     // f32 [NT,128]
static constexpr size_t O_QK2  = O_QK   + SZF((size_t)NT*128);
static constexpr size_t O_QQH  = O_QK2  + SZF((size_t)NT*128);      // bf16 [NT,128] x3
static constexpr size_t O_LQH  = O_QQH  + SZB((size_t)NT*128);
static constexpr size_t O_QKH  = O_LQH  + SZB((size_t)NT*128);
static constexpr size_t O_LKF  = O_QKH  + SZB((size_t)NT*128);      // f32 [NT,128]
static constexpr size_t O_LKTH = O_LKF  + SZF((size_t)NT*128);      // bf16 [bg,128,256]
static constexpr size_t O_ATTH = O_LKTH + SZB((size_t)NT*128);      // bf16 [bg,256,256]
static constexpr size_t O_KVF  = O_ATTH + SZB((size_t)64*256*256);  // f32 [bg,2048,128]
static constexpr size_t O_KVH  = O_KVF  + SZF((size_t)64*2048*128); // bf16 [bg,2048,128]
static constexpr size_t O_END  = O_KVH  + SZB((size_t)64*2048*128);
__device__ __align__(1024) unsigned char g_pool[O_END];

__device__ __forceinline__ uint32_t pack_bf2(float v0, float v1) {
    __nv_bfloat16 h0 = __float2bfloat16(v0), h1 = __float2bfloat16(v1);
    return ((uint32_t)__bfloat16_as_ushort(h1) << 16) | __bfloat16_as_ushort(h0);
}

// ================= elementwise / prep kernels =================
__global__ void shift_k(const float4* __restrict__ x, float4* __restrict__ nx) {
    long i = (long)blockIdx.x * blockDim.x + threadIdx.x;
    if (i >= (long)NT*(Dd/4)) return;
    int c4 = (int)(i % (Dd/4));
    int n  = (int)((i / (Dd/4)) % Nn);
    if (c4 < Dd/8) nx[i] = (n == 0) ? make_float4(0,0,0,0) : x[i - Dd/4];
    else           nx[i] = x[i];
}

__global__ void ln_bf16_k(const float* __restrict__ in, const float* __restrict__ g,
                          const float* __restrict__ b,
                          __nv_bfloat16* __restrict__ oh, int C) {
    long row = blockIdx.x;
    const float2* xr2 = (const float2*)(in + row * C);
    int C2 = C >> 1;
    float s = 0.f, s2 = 0.f;
    for (int i = threadIdx.x; i < C2; i += blockDim.x) {
        float2 v = xr2[i]; s += v.x + v.y; s2 += v.x*v.x + v.y*v.y;
    }
    #pragma unroll
    for (int o = 16; o; o >>= 1) {
        s  += __shfl_xor_sync(~0u, s,  o);
        s2 += __shfl_xor_sync(~0u, s2, o);
    }
    __shared__ float shs[8], shs2[8], smu, sinv;
    int w = threadIdx.x >> 5, l = threadIdx.x & 31;
    if (l == 0) { shs[w] = s; shs2[w] = s2; }
    __syncthreads();
    if (threadIdx.x == 0) {
        float ts = 0.f, ts2 = 0.f;
        for (int i = 0; i < (int)(blockDim.x >> 5); i++) { ts += shs[i]; ts2 += shs2[i]; }
        float mu = ts / C;
        smu = mu; sinv = rsqrtf(ts2 / C - mu*mu + 1e-5f);
    }
    __syncthreads();
    float mu = smu, inv = sinv;
    uint32_t* oh2 = (uint32_t*)(oh + row*C);
    const float2* g2 = (const float2*)g;
    const float2* b2 = (const float2*)b;
    for (int i = threadIdx.x; i < C2; i += blockDim.x) {
        float2 xv = xr2[i], gv = g2[i], bv = b2[i];
        float v0 = (xv.x - mu) * inv * gv.x + bv.x;
        float v1 = (xv.y - mu) * inv * gv.y + bv.y;
        oh2[i] = pack_bf2(v0, v1);
    }
}

// fused gating + LN(1024) -> bf16
__global__ void gate_ln_k(const float* __restrict__ att, const float* __restrict__ hid,
                          const float* __restrict__ g, const float* __restrict__ b,
                          __nv_bfloat16* __restrict__ oh) {
    long row = blockIdx.x;
    __shared__ float buf[1024];
    const float2* ar  = (const float2*)(att + row*HIDc);
    const float2* ar2 = (const float2*)(att + row*HIDc + Ee);
    const float2* hr  = (const float2*)(hid + row*HIDc);
    const float2* hr2 = (const float2*)(hid + row*HIDc + Ee);
    float s = 0.f, s2 = 0.f;
    for (int i = threadIdx.x; i < 512; i += blockDim.x) {
        float2 av = ar[i], au = ar2[i], v = hr[i], u = hr2[i];
        float t0 = au.x * v.x * (1.f / (1.f + expf(-(av.x * u.x))));
        float t1 = au.y * v.y * (1.f / (1.f + expf(-(av.y * u.y))));
        buf[2*i] = t0; buf[2*i+1] = t1;
        s += t0 + t1; s2 += t0*t0 + t1*t1;
    }
    #pragma unroll
    for (int o = 16; o; o >>= 1) {
        s  += __shfl_xor_sync(~0u, s,  o);
        s2 += __shfl_xor_sync(~0u, s2, o);
    }
    __shared__ float shs[8], shs2[8], smu, sinv;
    int w = threadIdx.x >> 5, l = threadIdx.x & 31;
    if (l == 0) { shs[w] = s; shs2[w] = s2; }
    __syncthreads();
    if (threadIdx.x == 0) {
        float ts = 0.f, ts2 = 0.f;
        for (int i = 0; i < (int)(blockDim.x >> 5); i++) { ts += shs[i]; ts2 += shs2[i]; }
        float mu = ts / 1024.f;
        smu = mu; sinv = rsqrtf(ts2 / 1024.f - mu*mu + 1e-5f);
    }
    __syncthreads();
    float mu = smu, inv = sinv;
    uint32_t* oh2 = (uint32_t*)(oh + row*1024);
    for (int i = threadIdx.x; i < 512; i += blockDim.x) {
        float v0 = (buf[2*i]   - mu) * inv * g[2*i]   + b[2*i];
        float v1 = (buf[2*i+1] - mu) * inv * g[2*i+1] + b[2*i+1];
        oh2[i] = pack_bf2(v0, v1);
    }
}

// vectorized transpose fp32 [R,C] -> bf16 [C,R], batched via blockIdx.z
__global__ void trans_bf16_k(const float* __restrict__ in,
                             __nv_bfloat16* __restrict__ oh, int R, int C) {
    __shared__ float s[32][36];
    size_t bz = (size_t)blockIdx.z * R * C;
    int c0 = blockIdx.x * 32, r0 = blockIdx.y * 32;
    int t = threadIdx.x;
    {
        int r = t >> 3, c4 = (t & 7) * 4;
        *(float4*)&s[r][c4] = *(const float4*)(in + bz + (size_t)(r0 + r)*C + c0 + c4);
    }
    __syncthreads();
    {
        int c = t & 31, rg = (t >> 5) * 4;
        uint32_t h01 = pack_bf2(s[rg][c],   s[rg+1][c]);
        uint32_t h23 = pack_bf2(s[rg+2][c], s[rg+3][c]);
        size_t o = bz + (size_t)(c0 + c)*R + r0 + rg;
        *(uint2*)(oh + o) = make_uint2(h01, h23);
    }
}

// float4 depthwise conv K=17 + residual (+ optional extra residual)
// If ht != nullptr (C==HIDc path), also emits bf16 group-transposed copy
// ht[b*Gg + n0/256][channel][n%256] with coalesced stores.
__global__ void dwconv4_k(const float4* __restrict__ h4, const float* __restrict__ dw,
                          const float4* __restrict__ extra4, float4* __restrict__ out4,
                          __nv_bfloat16* __restrict__ ht, int C) {
    const int CT4 = 16, NTile = 128, HALO = 8;
    __shared__ float4 sh[NTile + 2*HALO][CT4];
    __shared__ float4 sdw[KK][CT4];
    int b = blockIdx.z, n0 = blockIdx.y * NTile, c0 = blockIdx.x * CT4;
    int C4 = C >> 2;
    const float4* base = h4 + (size_t)b*Nn*C4 + c0;
    for (int idx = threadIdx.x; idx < (NTile + 2*HALO)*CT4; idx += blockDim.x) {
        int r = idx >> 4, c = idx & 15;
        int n = n0 - HALO + r;
        sh[r][c] = (n >= 0 && n < Nn) ? base[(size_t)n*C4 + c] : make_float4(0,0,0,0);
    }
    for (int idx = threadIdx.x; idx < KK*CT4; idx += blockDim.x) {
        int k = idx >> 4, c = idx & 15;
        const float* w = dw + k*C + (c0 + c)*4;
        sdw[k][c] = make_float4(w[0], w[1], w[2], w[3]);
    }
    __syncthreads();
    float4 accs[8];
    #pragma unroll
    for (int e = 0; e < 8; e++) {
        int idx = threadIdx.x + e*256;          // NTile*CT4 == 2048 == 8*256
        int r = idx >> 4, c = idx & 15;
        float4 acc = sh[r + HALO][c];
        #pragma unroll
        for (int k = 0; k < KK; k++) {
            float4 a = sh[r + k][c], w = sdw[k][c];
            acc.x += a.x*w.x; acc.y += a.y*w.y; acc.z += a.z*w.z; acc.w += a.w*w.w;
        }
        size_t o = (size_t)b*Nn*C4 + (size_t)(n0 + r)*C4 + c0 + c;
        if (extra4) {
            float4 ev = extra4[o];
            acc.x += ev.x; acc.y += ev.y; acc.z += ev.z; acc.w += ev.w;
        }
        out4[o] = acc;
        accs[e] = acc;
    }
    if (ht) {
        __syncthreads();
        float* sout = (float*)sh;               // reuse as [128][65] padded f32
        #pragma unroll
        for (int e = 0; e < 8; e++) {
            int idx = threadIdx.x + e*256;
            int r = idx >> 4, c = idx & 15;
            float* p = &sout[r*65 + c*4];
            p[0] = accs[e].x; p[1] = accs[e].y; p[2] = accs[e].z; p[3] = accs[e].w;
        }
        __syncthreads();
        int g = n0 >> 8, nloc = n0 & 255;
        size_t basebg = ((size_t)(b*Gg + g)*C + c0*4) * 256 + nloc;
        #pragma unroll
        for (int e = 0; e < 8; e++) {
            int idx = threadIdx.x + e*256;      // over 64 ch * 32 quad-rows
            int cc = idx >> 5, r4 = (idx & 31) * 4;
            float v0 = sout[(r4+0)*65 + cc];
            float v1 = sout[(r4+1)*65 + cc];
            float v2 = sout[(r4+2)*65 + cc];
            float v3 = sout[(r4+3)*65 + cc];
            *(uint2*)(ht + basebg + (size_t)cc*256 + r4) =
                make_uint2(pack_bf2(v0, v1), pack_bf2(v2, v3));
        }
    }
}

__global__ void qsplit_k(const float* __restrict__ qk, const float* __restrict__ gamma,
                         const float* __restrict__ beta,
                         __nv_bfloat16* qqh, __nv_bfloat16* lqh, __nv_bfloat16* qkh,
                         float* lkf) {
    long i2 = (long)blockIdx.x * blockDim.x + threadIdx.x;      // over NT*DQK/2
    if (i2 >= (long)NT*DQK/2) return;
    int d = (int)((i2 & 63) * 2);
    float2 v = ((const float2*)qk)[i2];
    ((uint32_t*)qqh)[i2] = pack_bf2(v.x * gamma[0*DQK + d]   + beta[0*DQK + d],
                                    v.y * gamma[0*DQK + d+1] + beta[0*DQK + d+1]);
    ((uint32_t*)lqh)[i2] = pack_bf2(v.x * gamma[1*DQK + d]   + beta[1*DQK + d],
                                    v.y * gamma[1*DQK + d+1] + beta[1*DQK + d+1]);
    ((uint32_t*)qkh)[i2] = pack_bf2(v.x * gamma[2*DQK + d]   + beta[2*DQK + d],
                                    v.y * gamma[2*DQK + d+1] + beta[2*DQK + d+1]);
    float2 lk;
    lk.x = v.x * gamma[3*DQK + d] + beta[3*DQK + d];
    lk.y = v.y * gamma[3*DQK + d+1] + beta[3*DQK + d+1];
    ((float2*)lkf)[i2] = lk;
}

__global__ void cumsum_bf16_k(const float* __restrict__ kvf,
                              __nv_bfloat16* __restrict__ oh) {
    const size_t S = (size_t)2048*128;
    long i2 = (long)blockIdx.x * blockDim.x + threadIdx.x;      // over Bb*S/2
    if (i2 >= (long)Bb*(S/2)) return;
    size_t b = (size_t)i2 / (S/2), r2 = (size_t)i2 % (S/2);
    size_t base2 = b*Gg*(S/2) + r2;
    float s0 = 0.f, s1 = 0.f;
    #pragma unroll
    for (int g = 0; g < Gg; g++) {
        size_t o2 = base2 + (size_t)g*(S/2);
        float2 v = ((const float2*)kvf)[o2];
        ((uint32_t*)oh)[o2] = pack_bf2(s0, s1);
        s0 += v.x; s1 += v.y;
    }
}

// ================= HMMA bf16 GEMM — two-part K, 128x128 tile, 2-stage ==========
// D[m,n] = sum_k A1[m,k]B1[n,k] (K1 chunks, TRIA applies)
//        + sum_k A2[m,k]B2[n,k] (K2 chunks), all K-major bf16.
#define LDA 72            // bf16 elems per smem row (64 data + 8 pad) = 144 B
#define STG_BYTES 36864   // one stage: A (18432) + B (18432)
#define GSMEM (2*STG_BYTES)

__global__ void __launch_bounds__(256, 2) gemm_k(
    const __nv_bfloat16* __restrict__ A1, const __nv_bfloat16* __restrict__ B1,
    const __nv_bfloat16* __restrict__ A2, const __nv_bfloat16* __restrict__ B2,
    float* C, __nv_bfloat16* Ch,
    int M, int N, int K1, int K2, const float* __restrict__ bias, float alpha, int flags,
    long long sA1, long long sB1, long long sA2, long long sB2, long long sC)
{
    extern __shared__ __align__(16) unsigned char smem[];
    uint32_t sbase = smem_to_u32(smem);
    int tid = threadIdx.x, lane = tid & 31, wid = tid >> 5;
    int wm = wid & 3, wn = wid >> 2;            // 4 (M) x 2 (N) warps
    int brow = blockIdx.y * 128, bcol = blockIdx.x * 128;
    long long bz = blockIdx.z;
    A1 += bz*sA1; B1 += bz*sB1;
    if (A2) { A2 += bz*sA2; B2 += bz*sB2; }
    if (C)  C  += bz*sC;
    if (Ch) Ch += bz*sC;

    // fully-masked score tile: zero-fill and exit
    if ((flags & F_SCORE) && bcol > brow) {
        uint4 z = make_uint4(0,0,0,0);
        for (int e = tid; e < 2048; e += 256) {
            int row = e >> 4, seg = e & 15;
            *(uint4*)(Ch + (size_t)(brow + row)*N + bcol + seg*8) = z;
        }
        return;
    }

    float acc[2][8][4];
    #pragma unroll
    for (int i = 0; i < 2; i++)
        #pragma unroll
        for (int j = 0; j < 8; j++)
            #pragma unroll
            for (int q = 0; q < 4; q++) acc[i][j][q] = 0.f;

    uint32_t aOff = (uint32_t)(((wm*32 + (lane & 15)) * LDA + (lane >> 4)*8) * 2);
    uint32_t bOff = (uint32_t)(((wn*64 + ((lane >> 4) & 1)*8 + (lane & 7)) * LDA
                                + ((lane >> 3) & 1)*8) * 2) + 18432;
    const int ldr = tid >> 3, lds2 = tid & 7;   // 8 x 16B segments per 144B row

    int KC1 = K1 >> 6;
    if (flags & F_TRIA) {                       // part-1 K <= brow+128
        int kc = (brow + 128) >> 6;
        if (kc < KC1) KC1 = kc;
    }
    const int KC2 = K2 >> 6;
    const int KC = KC1 + KC2;

    auto issue = [&](int it) {
        const __nv_bfloat16 *Ap, *Bp; int k0, Kst;
        if (it < KC1) { Ap = A1; Bp = B1; k0 = it << 6;          Kst = K1; }
        else          { Ap = A2; Bp = B2; k0 = (it - KC1) << 6;  Kst = K2; }
        uint32_t sa = sbase + (uint32_t)(it & 1)*STG_BYTES;
        #pragma unroll
        for (int e = 0; e < 4; e++) {
            int r = ldr + e*32;
            cp16(sa + (uint32_t)(r*144 + lds2*16),
                 Ap + (size_t)(brow + r)*Kst + k0 + lds2*8);
            cp16(sa + 18432u + (uint32_t)(r*144 + lds2*16),
                 Bp + (size_t)(bcol + r)*Kst + k0 + lds2*8);
        }
        CP_COMMIT();
    };

    issue(0);
    for (int it = 0; it < KC; ++it) {
        if (it + 1 < KC) { issue(it + 1); CP_WAIT(1); }
        else             { CP_WAIT(0); }
        __syncthreads();
        uint32_t stg = sbase + (uint32_t)(it & 1)*STG_BYTES;
        uint32_t aB = stg + aOff, bB = stg + bOff;
        #pragma unroll
        for (int kk = 0; kk < 4; kk++) {
            uint32_t af[2][4], bfr[4][4];
            #pragma unroll
            for (int i = 0; i < 2; i++)
                ldsm4(af[i], aB + (uint32_t)((i*16*LDA + kk*16) * 2));
            #pragma unroll
            for (int p = 0; p < 4; p++)
                ldsm4(bfr[p], bB + (uint32_t)((p*16*LDA + kk*16) * 2));
            #pragma unroll
            for (int i = 0; i < 2; i++)
                #pragma unroll
                for (int j = 0; j < 8; j++)
                    mma16816(acc[i][j], af[i], bfr[j>>1][(j&1)*2], bfr[j>>1][(j&1)*2+1]);
        }
        __syncthreads();
    }

    // ---- epilogue ----
    int g = lane >> 2, c2 = (lane & 3)*2;
    #pragma unroll
    for (int i = 0; i < 2; i++) {
        #pragma unroll
        for (int j = 0; j < 8; j++) {
            #pragma unroll
            for (int rr = 0; rr < 2; rr++) {
                int row = brow + wm*32 + i*16 + g + rr*8;
                int col = bcol + wn*64 + j*8 + c2;
                float v0 = acc[i][j][rr*2+0] * alpha;
                float v1 = acc[i][j][rr*2+1] * alpha;
                if (flags & F_SCORE) {
                    v0 = fmaxf(v0, 0.f); v0 *= v0;
                    v1 = fmaxf(v1, 0.f); v1 *= v1;
                    if (col     > row) v0 = 0.f;
                    if (col + 1 > row) v1 = 0.f;
                    *(uint32_t*)(Ch + (size_t)row*N + col) = pack_bf2(v0, v1);
                } else {
                    if (bias) { v0 += bias[col]; v1 += bias[col+1]; }
                    if (flags & F_SILU) {
                        v0 = v0 / (1.f + expf(-v0));
                        v1 = v1 / (1.f + expf(-v1));
                    }
                    *(float2*)(C + (size_t)row*N + col) = make_float2(v0, v1);
                }
            }
        }
    }
}

// ================= launcher =================
extern "C" void kernel_launch(void* const* d_in, const int* in_sizes, int n_in,
                              void* d_out, int out_size) {
    const float* x      = (const float*)d_in[0];
    const float* ln_h_g = (const float*)d_in[1];
    const float* ln_h_b = (const float*)d_in[2];
    const float* W_h    = (const float*)d_in[3];
    const float* b_h    = (const float*)d_in[4];
    const float* dw_h   = (const float*)d_in[5];
    const float* ln_qk_g= (const float*)d_in[6];
    const float* ln_qk_b= (const float*)d_in[7];
    const float* W_qk   = (const float*)d_in[8];
    const float* b_qk   = (const float*)d_in[9];
    const float* dw_qk  = (const float*)d_in[10];
    const float* gamma  = (const float*)d_in[11];
    const float* beta   = (const float*)d_in[12];
    const float* ln_o_g = (const float*)d_in[13];
    const float* ln_o_b = (const float*)d_in[14];
    const float* W_o    = (const float*)d_in[15];
    const float* b_o    = (const float*)d_in[16];
    const float* dw_o   = (const float*)d_in[17];
    float* out = (float*)d_out;

    unsigned char* pool;
    cudaGetSymbolAddress((void**)&pool, g_pool);
    float*         nx   = (float*)(pool + O_NX);
    __nv_bfloat16* lnH  = (__nv_bfloat16*)(pool + O_LNH);
    __nv_bfloat16* whTH = (__nv_bfloat16*)(pool + O_WHTH);
    __nv_bfloat16* wqTH = (__nv_bfloat16*)(pool + O_WQTH);
    __nv_bfloat16* woTH = (__nv_bfloat16*)(pool + O_WOTH);
    float*         bufA = (float*)(pool + O_BUFA);
    float*         hid  = (float*)(pool + O_HID);
    __nv_bfloat16* hTH  = (__nv_bfloat16*)(pool + O_HTH);
    float*         qk   = (float*)(pool + O_QK);
    float*         qk2  = (float*)(pool + O_QK2);
    __nv_bfloat16* qqH  = (__nv_bfloat16*)(pool + O_QQH);
    __nv_bfloat16* lqH  = (__nv_bfloat16*)(pool + O_LQH);
    __nv_bfloat16* qkH  = (__nv_bfloat16*)(pool + O_QKH);
    float*         lkF  = (float*)(pool + O_LKF);
    __nv_bfloat16* lkTH = (__nv_bfloat16*)(pool + O_LKTH);
    __nv_bfloat16* attH = (__nv_bfloat16*)(pool + O_ATTH);
    float*         kvF  = (float*)(pool + O_KVF);
    __nv_bfloat16* kvH  = (__nv_bfloat16*)(pool + O_KVH);
    float*         opre = nx;

    cudaFuncSetAttribute(gemm_k, cudaFuncAttributeMaxDynamicSharedMemorySize, GSMEM);

    // 1. token shift (float4)
    shift_k<<<(NT*(Dd/4) + 255)/256, 256>>>((const float4*)x, (float4*)nx);
    // 2. weight transposes -> bf16 [out,in] K-major
    trans_bf16_k<<<dim3(2048/32, 512/32, 1), 256>>>(W_h,  whTH, 512, 2048);
    trans_bf16_k<<<dim3(128/32,  512/32, 1), 256>>>(W_qk, wqTH, 512, 128);
    trans_bf16_k<<<dim3(512/32, 1024/32, 1), 256>>>(W_o,  woTH, 1024, 512);
    // 3. LN_h -> bf16
    ln_bf16_k<<<NT, 256>>>(nx, ln_h_g, ln_h_b, lnH, Dd);
    // 4. GEMM1 -> bufA (SiLU)
    gemm_k<<<dim3(16, 128, 1), 256, GSMEM>>>(lnH, whTH, nullptr, nullptr, bufA, nullptr,
        NT, HIDc, Dd, 0, b_h, 1.f, F_SILU, 0, 0, 0, 0, 0);
    // 5. dwconv -> hid, fused group-transpose -> hTH
    dwconv4_k<<<dim3(32, 16, Bb), 256>>>((const float4*)bufA, dw_h, nullptr,
                                         (float4*)hid, hTH, HIDc);
    // 6. LN_qk -> bf16
    ln_bf16_k<<<NT, 256>>>(nx, ln_qk_g, ln_qk_b, lnH, Dd);
    // 7. GEMM2 -> qk (SiLU)
    gemm_k<<<dim3(1, 128, 1), 256, GSMEM>>>(lnH, wqTH, nullptr, nullptr, qk, nullptr,
        NT, DQK, Dd, 0, b_qk, 1.f, F_SILU, 0, 0, 0, 0, 0);
    // 8. dwconv -> qk2
    dwconv4_k<<<dim3(2, 16, Bb), 256>>>((const float4*)qk, dw_qk, nullptr,
                                        (float4*)qk2, nullptr, DQK);
    // 9. offset-scale split
    qsplit_k<<<(NT*DQK/2 + 255)/256, 256>>>(qk2, gamma, beta, qqH, lqH, qkH, lkF);
    // 10. lin_k per-group transpose -> lkT [bg,128,256]
    trans_bf16_k<<<dim3(4, 8, 64), 256>>>(lkF, lkTH, 256, 128);
    // 11. scores -> attH (relu^2 causal, bf16)
    gemm_k<<<dim3(2, 2, 64), 256, GSMEM>>>(qqH, qkH, nullptr, nullptr, nullptr, attH,
        GRP, GRP, DQK, 0, nullptr, 1.f/GRP, F_SCORE,
        (long long)GRP*DQK, (long long)GRP*DQK, 0, 0, (long long)GRP*GRP);
    // 12. lin kv (coalesced): out[e,d] = sum_n hT[e,n]*lkT[d,n] / g
    gemm_k<<<dim3(1, 16, 64), 256, GSMEM>>>(hTH, lkTH, nullptr, nullptr, kvF, nullptr,
        HIDc, DQK, GRP, 0, nullptr, 1.f/GRP, 0,
        (long long)HIDc*GRP, (long long)DQK*GRP, 0, 0, (long long)HIDc*DQK);
    // 13. exclusive group cumsum -> kvH
    cumsum_bf16_k<<<(int)(((size_t)Bb*2048*64 + 255)/256), 256>>>(kvF, kvH);
    // 14. MERGED quad-out + lin-out: attn@hT^T (TRIA) + lin_q@kv^T -> bufA
    gemm_k<<<dim3(16, 2, 64), 256, GSMEM>>>(attH, hTH, lqH, kvH, bufA, nullptr,
        GRP, HIDc, GRP, DQK, nullptr, 1.f, F_TRIA,
        (long long)GRP*GRP, (long long)HIDc*GRP,
        (long long)GRP*DQK, (long long)HIDc*DQK, (long long)GRP*HIDc);
    // 15. fused gating + LN_o -> lnH
    gate_ln_k<<<NT, 256>>>(bufA, hid, ln_o_g, ln_o_b, lnH);
    // 16. GEMM3 -> opre (SiLU)
    gemm_k<<<dim3(4, 128, 1), 256, GSMEM>>>(lnH, woTH, nullptr, nullptr, opre, nullptr,
        NT, Dd, 2*Dd, 0, b_o, 1.f, F_SILU, 0, 0, 0, 0, 0);
    // 17. dwconv + x residual -> out
    dwconv4_k<<<dim3(8, 16, Bb), 256>>>((const float4*)opre, dw_o, (const float4*)x,
                                        (float4*)out, nullptr, Dd);
}